// round 4
// baseline (speedup 1.0000x reference)
#include <cuda_runtime.h>
#include <math.h>

// Problem dims (fixed by the dataset)
#define B 1024
#define S 64
#define E 256
#define H 512
#define V 128
#define C 32

#define BT    8            // batch rows per CTA tile
#define BP    4            // batch pairs (f32x2 packs 2 batch rows)
#define HPAIR 256          // h-pairs
#define NBLK  (B / BT)     // 128 CTAs
#define NGRP  4            // k-split groups
#define THR   (NGRP * 256) // 1024 threads
#define THRM  256          // mlp kernel threads

// dynamic smem layout for rnn_kernel
#define SM_HT2   0                          // ulonglong2 [H*2]          16 KB
#define SM_PB    (16384)                    // ulonglong2 [3*HPAIR*4]    48 KB
#define SM_INTS  (16384 + 49152)            // int orig[8], slen[8], xi[8]
#define RNN_SMEM (SM_INTS + 3 * BT * 4)

// Scratch (no allocations allowed -> __device__ globals)
__device__ float  g_P[V * H];                     // emb @ W_ih^T + b_ih + b_hh
__device__ float4 g_Wp[(H / 2) * (H / 2)];        // paired W_hh^T (1 MB)
__device__ float  g_W1T[H * H];                   // W1^T [k][h]
__device__ float  g_W2T[H * C];                   // W2^T [k][c]
__device__ float  g_last[B * H];                  // h at t=len-1, original order
__device__ int    g_sidx[B];
__device__ int    g_slen[B];

// ---------------------------------------------------------------------------
// f32x2 helpers
// ---------------------------------------------------------------------------
typedef unsigned long long ull;
__device__ __forceinline__ ull pk2(float x, float y) {
    ull r; asm("mov.b64 %0, {%1, %2};" : "=l"(r) : "f"(x), "f"(y)); return r;
}
__device__ __forceinline__ void upk2(ull v, float& x, float& y) {
    asm("mov.b64 {%0, %1}, %2;" : "=f"(x), "=f"(y) : "l"(v));
}
__device__ __forceinline__ void fma2(ull& d, ull a, ull b) {
    asm("fma.rn.f32x2 %0, %1, %2, %3;" : "=l"(d) : "l"(a), "l"(b), "l"(d));
}
__device__ __forceinline__ void add2(ull& d, ull a, ull b) {
    asm("add.rn.f32x2 %0, %1, %2;" : "=l"(d) : "l"(a), "l"(b));
}

// ---------------------------------------------------------------------------
// Kernel 1: P[v][h] = sum_e emb[v,e] * W_ih[h,e] + b_ih[h] + b_hh[h]
// ---------------------------------------------------------------------------
__global__ void precompute_P(const float* __restrict__ emb,
                             const float* __restrict__ W_ih,
                             const float* __restrict__ b_ih,
                             const float* __restrict__ b_hh) {
    __shared__ float es[E];
    const int v = blockIdx.x;
    const int h = threadIdx.x;
    if (h < E) es[h] = emb[v * E + h];
    __syncthreads();

    float acc = b_ih[h] + b_hh[h];
    const float4* w  = reinterpret_cast<const float4*>(W_ih + h * E);
    const float4* e4 = reinterpret_cast<const float4*>(es);
#pragma unroll 8
    for (int i = 0; i < E / 4; i++) {
        float4 a = e4[i], b = w[i];
        acc += a.x * b.x + a.y * b.y + a.z * b.z + a.w * b.w;
    }
    g_P[v * H + h] = acc;
}

// ---------------------------------------------------------------------------
// Kernel 2: stable rank sort of rows by length
// ---------------------------------------------------------------------------
__global__ void sort_by_len(const int* __restrict__ lens) {
    __shared__ int sl[B];
    const int i = threadIdx.x;
    sl[i] = lens[i];
    __syncthreads();
    const int my = sl[i];
    int rank = 0;
#pragma unroll 8
    for (int j = 0; j < B; j++) {
        int lj = sl[j];
        rank += (lj < my) || (lj == my && j < i);
    }
    g_sidx[rank] = i;
    g_slen[rank] = my;
}

// ---------------------------------------------------------------------------
// Kernel 3: build paired-k W_hh layout + W1^T + W2^T
// g_Wp[kp*HPAIR+hp] = {W[2kp][2hp], W[2kp][2hp+1], W[2kp+1][2hp], W[2kp+1][2hp+1]}
// ---------------------------------------------------------------------------
__global__ void transpose_all(const float* __restrict__ W_hh,
                              const float* __restrict__ W1,
                              const float* __restrict__ W2) {
    int idx = blockIdx.x * blockDim.x + threadIdx.x;
    if (idx < H * H) {
        int h = idx >> 9, k = idx & (H - 1);
        int kp = k >> 1, hp = h >> 1;
        reinterpret_cast<float*>(g_Wp)[(kp * HPAIR + hp) * 4 + (k & 1) * 2 + (h & 1)]
            = W_hh[idx];
    } else if (idx < 2 * H * H) {
        int j = idx - H * H;
        int h = j >> 9, k = j & (H - 1);
        g_W1T[k * H + h] = W1[j];
    } else {
        int j = idx - 2 * H * H;
        if (j < C * H) {
            int c = j >> 9, k = j & (H - 1);
            g_W2T[k * C + c] = W2[j];
        }
    }
}

// ---------------------------------------------------------------------------
// RNN inner compute: 4 kp (8 k) with weights in regs.
// hT2: [k][2] ulonglong2 (batch pairs). a0 = accum for h0, a1 for h1.
// ---------------------------------------------------------------------------
__device__ __forceinline__ void comp4(const ulonglong2* __restrict__ hT2, int k0,
                                      const ulonglong2 w[4], ull a0[BP], ull a1[BP]) {
#pragma unroll
    for (int j = 0; j < 4; j++) {
        const int k = k0 + 2 * j;
        float wl, wh;
        {
            ulonglong2 hA = hT2[k * 2], hB = hT2[k * 2 + 1];
            upk2(w[j].x, wl, wh);
            ull s0 = pk2(wl, wl), s1 = pk2(wh, wh);
            fma2(a0[0], hA.x, s0); fma2(a0[1], hA.y, s0);
            fma2(a0[2], hB.x, s0); fma2(a0[3], hB.y, s0);
            fma2(a1[0], hA.x, s1); fma2(a1[1], hA.y, s1);
            fma2(a1[2], hB.x, s1); fma2(a1[3], hB.y, s1);
        }
        {
            ulonglong2 hA = hT2[(k + 1) * 2], hB = hT2[(k + 1) * 2 + 1];
            upk2(w[j].y, wl, wh);
            ull s0 = pk2(wl, wl), s1 = pk2(wh, wh);
            fma2(a0[0], hA.x, s0); fma2(a0[1], hA.y, s0);
            fma2(a0[2], hB.x, s0); fma2(a0[3], hB.y, s0);
            fma2(a1[0], hA.x, s1); fma2(a1[1], hA.y, s1);
            fma2(a1[2], hB.x, s1); fma2(a1[3], hB.y, s1);
        }
    }
}

// ---------------------------------------------------------------------------
// Kernel 4: persistent RNN, 4-way k-split (1024 threads, 32 warps/SM).
// grp g covers k in [g*128, (g+1)*128).
// grp 0: + input-table init, final reduce, tanh, state update
// grp 1..3: write f32x2 partials to smem
// ---------------------------------------------------------------------------
__global__ void __launch_bounds__(THR, 1) rnn_kernel(const int* __restrict__ x_in) {
    extern __shared__ char smem[];
    ulonglong2* hT2 = reinterpret_cast<ulonglong2*>(smem + SM_HT2);  // [H*2]
    ulonglong2* pB  = reinterpret_cast<ulonglong2*>(smem + SM_PB);   // [3*HPAIR*4]
    int* orig = reinterpret_cast<int*>(smem + SM_INTS);
    int* slen = orig + BT;
    int* xi   = slen + BT;

    const int tid  = threadIdx.x;
    const int grp  = tid >> 8;              // 0..3
    const int hp   = tid & (HPAIR - 1);
    const int base = blockIdx.x * BT;

    if (tid < BT) {
        orig[tid] = g_sidx[base + tid];
        slen[tid] = g_slen[base + tid];
    }
    for (int i = tid; i < H * 2; i += THR) hT2[i] = make_ulonglong2(0ull, 0ull);
    __syncthreads();

    int tmax = 0;
#pragma unroll
    for (int b = 0; b < BT; b++) tmax = max(tmax, slen[b]);

    // this group's W columns: kp in [grp*64, grp*64+64), this thread's hp
    const ulonglong2* Wp =
        reinterpret_cast<const ulonglong2*>(g_Wp) + (grp * 64) * HPAIR + hp;
    const int kbase = grp * 128;            // global k base for this group

    for (int t = 0; t < tmax; t++) {
        if (tid < BT) xi[tid] = x_in[orig[tid] * S + t];
        __syncthreads();    // (1) xi ready; hT2 from previous epilogue visible

        ull a0[BP], a1[BP];
        if (grp == 0) {
            float pl[BT], ph[BT];
#pragma unroll
            for (int b = 0; b < BT; b++) {
                float2 p = __ldg(reinterpret_cast<const float2*>(g_P + xi[b] * H) + hp);
                pl[b] = p.x; ph[b] = p.y;
            }
#pragma unroll
            for (int bp = 0; bp < BP; bp++) {
                a0[bp] = pk2(pl[2 * bp], pl[2 * bp + 1]);
                a1[bp] = pk2(ph[2 * bp], ph[2 * bp + 1]);
            }
        } else {
#pragma unroll
            for (int bp = 0; bp < BP; bp++) { a0[bp] = 0ull; a1[bp] = 0ull; }
        }

        // 64 kp for this group, 8-kp chunks, double-buffered W prefetch
        ulonglong2 wA[4], wB[4];
#pragma unroll
        for (int j = 0; j < 4; j++) wA[j] = __ldg(Wp + j * HPAIR);
#pragma unroll 1
        for (int c = 0; c < 64; c += 8) {
#pragma unroll
            for (int j = 0; j < 4; j++) wB[j] = __ldg(Wp + (c + 4 + j) * HPAIR);
            comp4(hT2, kbase + 2 * c, wA, a0, a1);
            const int nc = (c + 8) & 63;    // wrap-around dummy on last iter
#pragma unroll
            for (int j = 0; j < 4; j++) wA[j] = __ldg(Wp + (nc + j) * HPAIR);
            comp4(hT2, kbase + 2 * (c + 4), wB, a0, a1);
        }

        if (grp != 0) {
            ulonglong2* dst = pB + (grp - 1) * (HPAIR * 4) + hp * 4;
            dst[0] = make_ulonglong2(a0[0], a0[1]);
            dst[1] = make_ulonglong2(a0[2], a0[3]);
            dst[2] = make_ulonglong2(a1[0], a1[1]);
            dst[3] = make_ulonglong2(a1[2], a1[3]);
        }
        __syncthreads();    // (2) partials visible; all hT2 reads complete

        if (grp == 0) {
#pragma unroll
            for (int g = 0; g < 3; g++) {
                const ulonglong2* src = pB + g * (HPAIR * 4) + hp * 4;
                ulonglong2 q0 = src[0], q1 = src[1], q2 = src[2], q3 = src[3];
                add2(a0[0], a0[0], q0.x); add2(a0[1], a0[1], q0.y);
                add2(a0[2], a0[2], q1.x); add2(a0[3], a0[3], q1.y);
                add2(a1[0], a1[0], q2.x); add2(a1[1], a1[1], q2.y);
                add2(a1[2], a1[2], q3.x); add2(a1[3], a1[3], q3.y);
            }

            float v0[BT], v1[BT];
#pragma unroll
            for (int bp = 0; bp < BP; bp++) {
                float x, y;
                upk2(a0[bp], x, y);
                v0[2 * bp] = tanhf(x); v0[2 * bp + 1] = tanhf(y);
                upk2(a1[bp], x, y);
                v1[2 * bp] = tanhf(x); v1[2 * bp + 1] = tanhf(y);
            }
            hT2[(2 * hp) * 2] =
                make_ulonglong2(pk2(v0[0], v0[1]), pk2(v0[2], v0[3]));
            hT2[(2 * hp) * 2 + 1] =
                make_ulonglong2(pk2(v0[4], v0[5]), pk2(v0[6], v0[7]));
            hT2[(2 * hp + 1) * 2] =
                make_ulonglong2(pk2(v1[0], v1[1]), pk2(v1[2], v1[3]));
            hT2[(2 * hp + 1) * 2 + 1] =
                make_ulonglong2(pk2(v1[4], v1[5]), pk2(v1[6], v1[7]));

#pragma unroll
            for (int b = 0; b < BT; b++) {
                if (t == slen[b] - 1) {
                    reinterpret_cast<float2*>(g_last + orig[b] * H)[hp] =
                        make_float2(v0[b], v1[b]);
                }
            }
        }
        // next iteration's sync (1) orders the hT2 writes before group reads
    }
}

// ---------------------------------------------------------------------------
// MLP helpers (k-major W, unpaired)
// ---------------------------------------------------------------------------
#define HP (H / 2)
__device__ __forceinline__ void load8(const ull* __restrict__ WTu, int k, ull w[8]) {
#pragma unroll
    for (int j = 0; j < 8; j++) w[j] = __ldg(WTu + (unsigned)(k + j) * HP);
}
__device__ __forceinline__ void compute8(const ulonglong2* __restrict__ hT, int k0,
                                         const ull w[8], ull a0[BP], ull a1[BP]) {
#pragma unroll
    for (int j = 0; j < 8; j++) {
        ulonglong2 hA = hT[(k0 + j) * 2];
        ulonglong2 hB = hT[(k0 + j) * 2 + 1];
        float wl, wh;
        upk2(w[j], wl, wh);
        ull s0 = pk2(wl, wl), s1 = pk2(wh, wh);
        fma2(a0[0], hA.x, s0); fma2(a0[1], hA.y, s0);
        fma2(a0[2], hB.x, s0); fma2(a0[3], hB.y, s0);
        fma2(a1[0], hA.x, s1); fma2(a1[1], hA.y, s1);
        fma2(a1[2], hB.x, s1); fma2(a1[3], hB.y, s1);
    }
}
__device__ __forceinline__ void gemm_k512(const ull* __restrict__ WTu,
                                          const ulonglong2* __restrict__ hT,
                                          ull a0[BP], ull a1[BP]) {
    ull wA[8], wB[8];
    load8(WTu, 0, wA);
#pragma unroll 1
    for (int k0 = 0; k0 < H; k0 += 16) {
        load8(WTu, k0 + 8, wB);
        compute8(hT, k0, wA, a0, a1);
        int kn = (k0 + 16 < H) ? k0 + 16 : 0;
        load8(WTu, kn, wA);
        compute8(hT, k0 + 8, wB, a0, a1);
    }
}

// ---------------------------------------------------------------------------
// Kernel 5: MLP head
// ---------------------------------------------------------------------------
__global__ void __launch_bounds__(THRM) mlp_kernel(const float* __restrict__ b1,
                                                   const float* __restrict__ b2,
                                                   float* __restrict__ out) {
    __shared__ ulonglong2 hT[H * 2];
    __shared__ float hlin[BT * H];

    const int tid  = threadIdx.x;
    const int base = blockIdx.x * BT;

    float* hTf = reinterpret_cast<float*>(hT);
    for (int i = tid; i < BT * H; i += THRM) {
        int b = i >> 9, k = i & (H - 1);
        hTf[k * BT + b] = g_last[(base + b) * H + k];
    }
    __syncthreads();

    const ull* WTu = reinterpret_cast<const ull*>(g_W1T) + tid;

    float b1l = __ldg(b1 + 2 * tid), b1h = __ldg(b1 + 2 * tid + 1);
    ull a0[BP], a1[BP];
#pragma unroll
    for (int bp = 0; bp < BP; bp++) {
        a0[bp] = pk2(b1l, b1l);
        a1[bp] = pk2(b1h, b1h);
    }

    gemm_k512(WTu, hT, a0, a1);

#pragma unroll
    for (int bp = 0; bp < BP; bp++) {
        float x, y;
        upk2(a0[bp], x, y);
        float r0e = fmaxf(x, 0.f), r0o = fmaxf(y, 0.f);
        upk2(a1[bp], x, y);
        float r1e = fmaxf(x, 0.f), r1o = fmaxf(y, 0.f);
        reinterpret_cast<float2*>(hlin + (2 * bp) * H)[tid]     = make_float2(r0e, r1e);
        reinterpret_cast<float2*>(hlin + (2 * bp + 1) * H)[tid] = make_float2(r0o, r1o);
    }
    __syncthreads();

    const int b = tid >> 5;
    const int c = tid & 31;
    float acc = __ldg(b2 + c);
    const float* hb = hlin + b * H;
#pragma unroll 4
    for (int k = 0; k < H; k += 4) {
        float4 hv = *reinterpret_cast<const float4*>(hb + k);
        acc += hv.x * __ldg(g_W2T + (k + 0) * C + c);
        acc += hv.y * __ldg(g_W2T + (k + 1) * C + c);
        acc += hv.z * __ldg(g_W2T + (k + 2) * C + c);
        acc += hv.w * __ldg(g_W2T + (k + 3) * C + c);
    }
    out[(base + b) * C + c] = acc;
}

// ---------------------------------------------------------------------------
extern "C" void kernel_launch(void* const* d_in, const int* in_sizes, int n_in,
                              void* d_out, int out_size) {
    const int*   x_in   = (const int*)  d_in[0];
    const int*   x_lens = (const int*)  d_in[1];
    const float* emb    = (const float*)d_in[2];
    const float* W_ih   = (const float*)d_in[3];
    const float* b_ih   = (const float*)d_in[4];
    const float* W_hh   = (const float*)d_in[5];
    const float* b_hh   = (const float*)d_in[6];
    const float* W1w    = (const float*)d_in[7];
    const float* b1     = (const float*)d_in[8];
    const float* W2w    = (const float*)d_in[9];
    const float* b2     = (const float*)d_in[10];
    float* out = (float*)d_out;

    cudaFuncSetAttribute(rnn_kernel,
                         cudaFuncAttributeMaxDynamicSharedMemorySize, RNN_SMEM);

    precompute_P<<<V, H>>>(emb, W_ih, b_ih, b_hh);
    sort_by_len<<<1, B>>>(x_lens);
    int tgrid = (2 * H * H + C * H + 255) / 256;
    transpose_all<<<tgrid, 256>>>(W_hh, W1w, W2w);
    rnn_kernel<<<NBLK, THR, RNN_SMEM>>>(x_in);
    mlp_kernel<<<NBLK, THRM>>>(b1, b2, out);
}

// round 5
// speedup vs baseline: 1.0494x; 1.0494x over previous
#include <cuda_runtime.h>
#include <math.h>

// Problem dims (fixed by the dataset)
#define B 1024
#define S 64
#define E 256
#define H 512
#define V 128
#define C 32

#define BT    8            // batch rows per CTA tile
#define BP    4            // batch pairs (f32x2 packs 2 batch rows)
#define HPAIR 256          // h-pairs
#define NBLK  (B / BT)     // 128 CTAs
#define NGRP  4            // k-split groups
#define THR   (NGRP * 256) // 1024 threads
#define THRM  256          // mlp kernel threads

#define PBSTRIDE 34        // ull stride per hp row in partial buffer (2 pad)

// dynamic smem layout for rnn_kernel
#define SM_HT2   0                              // ulonglong2[H*2]   16384 B
#define SM_PB    16384                          // ull[256*34]       69632 B
#define SM_INTS  (16384 + 69632)                // orig[8],slen[8],xi[8]
#define RNN_SMEM (SM_INTS + 3 * BT * 4)

// Scratch (no allocations allowed -> __device__ globals)
__device__ float  g_P[V * H];                   // emb @ W_ih^T + b_ih + b_hh
__device__ float4 g_Wp[(H / 2) * (H / 2)];      // paired W_hh^T (1 MB)
__device__ float  g_W1T[H * H];                 // W1^T [k][h]
__device__ float  g_W2T[H * C];                 // W2^T [k][c]
__device__ float  g_last[B * H];                // h at t=len-1, original order
__device__ int    g_sidx[B];
__device__ int    g_slen[B];

// ---------------------------------------------------------------------------
// f32x2 helpers
// ---------------------------------------------------------------------------
typedef unsigned long long ull;
__device__ __forceinline__ ull pk2(float x, float y) {
    ull r; asm("mov.b64 %0, {%1, %2};" : "=l"(r) : "f"(x), "f"(y)); return r;
}
__device__ __forceinline__ void upk2(ull v, float& x, float& y) {
    asm("mov.b64 {%0, %1}, %2;" : "=f"(x), "=f"(y) : "l"(v));
}
__device__ __forceinline__ void fma2(ull& d, ull a, ull b) {
    asm("fma.rn.f32x2 %0, %1, %2, %3;" : "=l"(d) : "l"(a), "l"(b), "l"(d));
}
__device__ __forceinline__ void add2(ull& d, ull a, ull b) {
    asm("add.rn.f32x2 %0, %1, %2;" : "=l"(d) : "l"(a), "l"(b));
}

// ---------------------------------------------------------------------------
// Kernel 1: P[v][h] = sum_e emb[v,e] * W_ih[h,e] + b_ih[h] + b_hh[h]
// ---------------------------------------------------------------------------
__global__ void precompute_P(const float* __restrict__ emb,
                             const float* __restrict__ W_ih,
                             const float* __restrict__ b_ih,
                             const float* __restrict__ b_hh) {
    __shared__ float es[E];
    const int v = blockIdx.x;
    const int h = threadIdx.x;
    if (h < E) es[h] = emb[v * E + h];
    __syncthreads();

    float acc = b_ih[h] + b_hh[h];
    const float4* w  = reinterpret_cast<const float4*>(W_ih + h * E);
    const float4* e4 = reinterpret_cast<const float4*>(es);
#pragma unroll 8
    for (int i = 0; i < E / 4; i++) {
        float4 a = e4[i], b = w[i];
        acc += a.x * b.x + a.y * b.y + a.z * b.z + a.w * b.w;
    }
    g_P[v * H + h] = acc;
}

// ---------------------------------------------------------------------------
// Kernel 2: stable rank sort of rows by length
// ---------------------------------------------------------------------------
__global__ void sort_by_len(const int* __restrict__ lens) {
    __shared__ int sl[B];
    const int i = threadIdx.x;
    sl[i] = lens[i];
    __syncthreads();
    const int my = sl[i];
    int rank = 0;
#pragma unroll 8
    for (int j = 0; j < B; j++) {
        int lj = sl[j];
        rank += (lj < my) || (lj == my && j < i);
    }
    g_sidx[rank] = i;
    g_slen[rank] = my;
}

// ---------------------------------------------------------------------------
// Kernel 3: build paired-k W_hh layout + W1^T + W2^T
// g_Wp[kp*HPAIR+hp] = {W[2kp][2hp], W[2kp][2hp+1], W[2kp+1][2hp], W[2kp+1][2hp+1]}
// ---------------------------------------------------------------------------
__global__ void transpose_all(const float* __restrict__ W_hh,
                              const float* __restrict__ W1,
                              const float* __restrict__ W2) {
    int idx = blockIdx.x * blockDim.x + threadIdx.x;
    if (idx < H * H) {
        int h = idx >> 9, k = idx & (H - 1);
        int kp = k >> 1, hp = h >> 1;
        reinterpret_cast<float*>(g_Wp)[(kp * HPAIR + hp) * 4 + (k & 1) * 2 + (h & 1)]
            = W_hh[idx];
    } else if (idx < 2 * H * H) {
        int j = idx - H * H;
        int h = j >> 9, k = j & (H - 1);
        g_W1T[k * H + h] = W1[j];
    } else {
        int j = idx - 2 * H * H;
        if (j < C * H) {
            int c = j >> 9, k = j & (H - 1);
            g_W2T[k * C + c] = W2[j];
        }
    }
}

// ---------------------------------------------------------------------------
// RNN inner compute: 4 kp (8 k) with weights in regs.
// hT2: [k][2] ulonglong2 (batch pairs). a0 = accum for h0, a1 for h1.
// ---------------------------------------------------------------------------
__device__ __forceinline__ void comp4(const ulonglong2* __restrict__ hT2, int k0,
                                      const ulonglong2 w[4], ull a0[BP], ull a1[BP]) {
#pragma unroll
    for (int j = 0; j < 4; j++) {
        const int k = k0 + 2 * j;
        float wl, wh;
        {
            ulonglong2 hA = hT2[k * 2], hB = hT2[k * 2 + 1];
            upk2(w[j].x, wl, wh);
            ull s0 = pk2(wl, wl), s1 = pk2(wh, wh);
            fma2(a0[0], hA.x, s0); fma2(a0[1], hA.y, s0);
            fma2(a0[2], hB.x, s0); fma2(a0[3], hB.y, s0);
            fma2(a1[0], hA.x, s1); fma2(a1[1], hA.y, s1);
            fma2(a1[2], hB.x, s1); fma2(a1[3], hB.y, s1);
        }
        {
            ulonglong2 hA = hT2[(k + 1) * 2], hB = hT2[(k + 1) * 2 + 1];
            upk2(w[j].y, wl, wh);
            ull s0 = pk2(wl, wl), s1 = pk2(wh, wh);
            fma2(a0[0], hA.x, s0); fma2(a0[1], hA.y, s0);
            fma2(a0[2], hB.x, s0); fma2(a0[3], hB.y, s0);
            fma2(a1[0], hA.x, s1); fma2(a1[1], hA.y, s1);
            fma2(a1[2], hB.x, s1); fma2(a1[3], hB.y, s1);
        }
    }
}

// ---------------------------------------------------------------------------
// Kernel 4: persistent RNN, 4-way k-split, fully distributed epilogue.
// GEMM phase: group g covers k in [g*128, (g+1)*128), ALL groups write
//             f32x2 partials to pB (padded layout, conflict-free STS).
// Epilogue:   all 1024 threads: thread = (h = tid>>1, q = tid&1) reduces
//             4 partials + P term, 4x tanh, one STS.128 state write.
// ---------------------------------------------------------------------------
__global__ void __launch_bounds__(THR, 1) rnn_kernel(const int* __restrict__ x_in) {
    extern __shared__ char smem[];
    ulonglong2* hT2 = reinterpret_cast<ulonglong2*>(smem + SM_HT2);  // [H*2]
    ull*        pB  = reinterpret_cast<ull*>(smem + SM_PB);          // [256*34]
    int* orig = reinterpret_cast<int*>(smem + SM_INTS);
    int* slen = orig + BT;
    int* xi   = slen + BT;

    const int tid  = threadIdx.x;
    const int grp  = tid >> 8;               // 0..3 (GEMM role)
    const int hp   = tid & (HPAIR - 1);
    const int base = blockIdx.x * BT;

    // epilogue role: h = tid>>1 (0..511), q = tid&1 (batch quad)
    const int eh   = tid >> 1;
    const int eq   = tid & 1;
    const int ehp  = eh >> 1;
    const int epar = eh & 1;

    if (tid < BT) {
        orig[tid] = g_sidx[base + tid];
        slen[tid] = g_slen[base + tid];
    }
    for (int i = tid; i < H * 2; i += THR) hT2[i] = make_ulonglong2(0ull, 0ull);
    __syncthreads();

    int tmax = 0;
#pragma unroll
    for (int b = 0; b < BT; b++) tmax = max(tmax, slen[b]);

    const ulonglong2* Wp =
        reinterpret_cast<const ulonglong2*>(g_Wp) + (grp * 64) * HPAIR + hp;
    const int kbase = grp * 128;

    ull*       myPB = pB + hp * PBSTRIDE + grp * 8;            // GEMM write base
    const ull* ePB  = pB + ehp * PBSTRIDE + epar * 4 + eq * 2; // epilogue read base

    for (int t = 0; t < tmax; t++) {
        if (tid < BT) xi[tid] = x_in[orig[tid] * S + t];
        __syncthreads();    // (1) xi ready; hT2 from previous epilogue visible

        // early P prefetch for this thread's epilogue outputs (latency hidden
        // behind the GEMM below)
        const int xb0 = xi[4 * eq + 0], xb1 = xi[4 * eq + 1];
        const int xb2 = xi[4 * eq + 2], xb3 = xi[4 * eq + 3];
        float pf0 = __ldg(g_P + xb0 * H + eh);
        float pf1 = __ldg(g_P + xb1 * H + eh);
        float pf2 = __ldg(g_P + xb2 * H + eh);
        float pf3 = __ldg(g_P + xb3 * H + eh);

        ull a0[BP], a1[BP];
#pragma unroll
        for (int bp = 0; bp < BP; bp++) { a0[bp] = 0ull; a1[bp] = 0ull; }

        // 64 kp for this group, 8-kp chunks, double-buffered W prefetch
        ulonglong2 wA[4], wB[4];
#pragma unroll
        for (int j = 0; j < 4; j++) wA[j] = __ldg(Wp + j * HPAIR);
#pragma unroll 1
        for (int c = 0; c < 64; c += 8) {
#pragma unroll
            for (int j = 0; j < 4; j++) wB[j] = __ldg(Wp + (c + 4 + j) * HPAIR);
            comp4(hT2, kbase + 2 * c, wA, a0, a1);
            const int nc = (c + 8) & 63;    // wrap-around dummy on last iter
#pragma unroll
            for (int j = 0; j < 4; j++) wA[j] = __ldg(Wp + (nc + j) * HPAIR);
            comp4(hT2, kbase + 2 * (c + 4), wB, a0, a1);
        }

        // all groups write partials (lane stride 34 ull -> conflict-free STS.128)
        *reinterpret_cast<ulonglong2*>(myPB + 0) = make_ulonglong2(a0[0], a0[1]);
        *reinterpret_cast<ulonglong2*>(myPB + 2) = make_ulonglong2(a0[2], a0[3]);
        *reinterpret_cast<ulonglong2*>(myPB + 4) = make_ulonglong2(a1[0], a1[1]);
        *reinterpret_cast<ulonglong2*>(myPB + 6) = make_ulonglong2(a1[2], a1[3]);
        __syncthreads();    // (2) partials visible; all hT2 reads complete

        // ---- distributed epilogue: every thread handles (h=eh, batches 4q..4q+3)
        ulonglong2 r0 = *reinterpret_cast<const ulonglong2*>(ePB);
        ulonglong2 r1 = *reinterpret_cast<const ulonglong2*>(ePB + 8);
        ulonglong2 r2 = *reinterpret_cast<const ulonglong2*>(ePB + 16);
        ulonglong2 r3 = *reinterpret_cast<const ulonglong2*>(ePB + 24);
        ull s01 = r0.x, s23 = r0.y;
        add2(s01, s01, r1.x); add2(s23, s23, r1.y);
        add2(s01, s01, r2.x); add2(s23, s23, r2.y);
        add2(s01, s01, r3.x); add2(s23, s23, r3.y);
        add2(s01, s01, pk2(pf0, pf1));
        add2(s23, s23, pk2(pf2, pf3));

        float x0, x1, x2, x3;
        upk2(s01, x0, x1);
        upk2(s23, x2, x3);
        const float v0 = tanhf(x0), v1 = tanhf(x1);
        const float v2 = tanhf(x2), v3 = tanhf(x3);

        // state write: hT2[k=eh][q] (consecutive tid -> consecutive 16B, no conflicts)
        hT2[eh * 2 + eq] = make_ulonglong2(pk2(v0, v1), pk2(v2, v3));

        // terminal-state stores
        {
            const int b0 = 4 * eq;
            if (t == slen[b0 + 0] - 1) g_last[orig[b0 + 0] * H + eh] = v0;
            if (t == slen[b0 + 1] - 1) g_last[orig[b0 + 1] * H + eh] = v1;
            if (t == slen[b0 + 2] - 1) g_last[orig[b0 + 2] * H + eh] = v2;
            if (t == slen[b0 + 3] - 1) g_last[orig[b0 + 3] * H + eh] = v3;
        }
        // next iteration's sync (1) orders hT2 writes before GEMM reads,
        // and pB reads above before next GEMM's pB writes.
    }
}

// ---------------------------------------------------------------------------
// MLP helpers (k-major W, unpaired)
// ---------------------------------------------------------------------------
#define HP (H / 2)
__device__ __forceinline__ void load8(const ull* __restrict__ WTu, int k, ull w[8]) {
#pragma unroll
    for (int j = 0; j < 8; j++) w[j] = __ldg(WTu + (unsigned)(k + j) * HP);
}
__device__ __forceinline__ void compute8(const ulonglong2* __restrict__ hT, int k0,
                                         const ull w[8], ull a0[BP], ull a1[BP]) {
#pragma unroll
    for (int j = 0; j < 8; j++) {
        ulonglong2 hA = hT[(k0 + j) * 2];
        ulonglong2 hB = hT[(k0 + j) * 2 + 1];
        float wl, wh;
        upk2(w[j], wl, wh);
        ull s0 = pk2(wl, wl), s1 = pk2(wh, wh);
        fma2(a0[0], hA.x, s0); fma2(a0[1], hA.y, s0);
        fma2(a0[2], hB.x, s0); fma2(a0[3], hB.y, s0);
        fma2(a1[0], hA.x, s1); fma2(a1[1], hA.y, s1);
        fma2(a1[2], hB.x, s1); fma2(a1[3], hB.y, s1);
    }
}
__device__ __forceinline__ void gemm_k512(const ull* __restrict__ WTu,
                                          const ulonglong2* __restrict__ hT,
                                          ull a0[BP], ull a1[BP]) {
    ull wA[8], wB[8];
    load8(WTu, 0, wA);
#pragma unroll 1
    for (int k0 = 0; k0 < H; k0 += 16) {
        load8(WTu, k0 + 8, wB);
        compute8(hT, k0, wA, a0, a1);
        int kn = (k0 + 16 < H) ? k0 + 16 : 0;
        load8(WTu, kn, wA);
        compute8(hT, k0 + 8, wB, a0, a1);
    }
}

// ---------------------------------------------------------------------------
// Kernel 5: MLP head
// ---------------------------------------------------------------------------
__global__ void __launch_bounds__(THRM) mlp_kernel(const float* __restrict__ b1,
                                                   const float* __restrict__ b2,
                                                   float* __restrict__ out) {
    __shared__ ulonglong2 hT[H * 2];
    __shared__ float hlin[BT * H];

    const int tid  = threadIdx.x;
    const int base = blockIdx.x * BT;

    float* hTf = reinterpret_cast<float*>(hT);
    for (int i = tid; i < BT * H; i += THRM) {
        int b = i >> 9, k = i & (H - 1);
        hTf[k * BT + b] = g_last[(base + b) * H + k];
    }
    __syncthreads();

    const ull* WTu = reinterpret_cast<const ull*>(g_W1T) + tid;

    float b1l = __ldg(b1 + 2 * tid), b1h = __ldg(b1 + 2 * tid + 1);
    ull a0[BP], a1[BP];
#pragma unroll
    for (int bp = 0; bp < BP; bp++) {
        a0[bp] = pk2(b1l, b1l);
        a1[bp] = pk2(b1h, b1h);
    }

    gemm_k512(WTu, hT, a0, a1);

#pragma unroll
    for (int bp = 0; bp < BP; bp++) {
        float x, y;
        upk2(a0[bp], x, y);
        float r0e = fmaxf(x, 0.f), r0o = fmaxf(y, 0.f);
        upk2(a1[bp], x, y);
        float r1e = fmaxf(x, 0.f), r1o = fmaxf(y, 0.f);
        reinterpret_cast<float2*>(hlin + (2 * bp) * H)[tid]     = make_float2(r0e, r1e);
        reinterpret_cast<float2*>(hlin + (2 * bp + 1) * H)[tid] = make_float2(r0o, r1o);
    }
    __syncthreads();

    const int b = tid >> 5;
    const int c = tid & 31;
    float acc = __ldg(b2 + c);
    const float* hb = hlin + b * H;
#pragma unroll 4
    for (int k = 0; k < H; k += 4) {
        float4 hv = *reinterpret_cast<const float4*>(hb + k);
        acc += hv.x * __ldg(g_W2T + (k + 0) * C + c);
        acc += hv.y * __ldg(g_W2T + (k + 1) * C + c);
        acc += hv.z * __ldg(g_W2T + (k + 2) * C + c);
        acc += hv.w * __ldg(g_W2T + (k + 3) * C + c);
    }
    out[(base + b) * C + c] = acc;
}

// ---------------------------------------------------------------------------
extern "C" void kernel_launch(void* const* d_in, const int* in_sizes, int n_in,
                              void* d_out, int out_size) {
    const int*   x_in   = (const int*)  d_in[0];
    const int*   x_lens = (const int*)  d_in[1];
    const float* emb    = (const float*)d_in[2];
    const float* W_ih   = (const float*)d_in[3];
    const float* b_ih   = (const float*)d_in[4];
    const float* W_hh   = (const float*)d_in[5];
    const float* b_hh   = (const float*)d_in[6];
    const float* W1w    = (const float*)d_in[7];
    const float* b1     = (const float*)d_in[8];
    const float* W2w    = (const float*)d_in[9];
    const float* b2     = (const float*)d_in[10];
    float* out = (float*)d_out;

    cudaFuncSetAttribute(rnn_kernel,
                         cudaFuncAttributeMaxDynamicSharedMemorySize, RNN_SMEM);

    precompute_P<<<V, H>>>(emb, W_ih, b_ih, b_hh);
    sort_by_len<<<1, B>>>(x_lens);
    int tgrid = (2 * H * H + C * H + 255) / 256;
    transpose_all<<<tgrid, 256>>>(W_hh, W1w, W2w);
    rnn_kernel<<<NBLK, THR, RNN_SMEM>>>(x_in);
    mlp_kernel<<<NBLK, THRM>>>(b1, b2, out);
}

// round 6
// speedup vs baseline: 1.4468x; 1.3787x over previous
#include <cuda_runtime.h>
#include <math.h>

// Problem dims (fixed by the dataset)
#define B 1024
#define S 64
#define E 256
#define H 512
#define V 128
#define C 32

#define BT    8            // batch rows (mlp tile)
#define BP    4
#define HPAIR 256          // h-pairs
#define NGRP  4            // k-split groups
#define THR   (NGRP * 256) // 1024 threads
#define THRM  256          // mlp kernel threads

// bucketed rnn grid: 86 CTAs of 4 rows (longest) + 85 CTAs of 8 rows
#define N_CTA4  86
#define N_CTA8  85
#define RNN_GRID (N_CTA4 + N_CTA8)   // 171

// dynamic smem (worst case = NB=8 path):
// hT2: 512*(8/2)*8 = 16384 ; pB: 256*34*8 = 69632 ; ints: 96
#define RNN_SMEM (16384 + 69632 + 96)

// Scratch (no allocations allowed -> __device__ globals)
__device__ float  g_P[V * H];                   // emb @ W_ih^T + b_ih + b_hh
__device__ float4 g_Wp[(H / 2) * (H / 2)];      // paired W_hh^T (1 MB)
__device__ float  g_W1T[H * H];                 // W1^T [k][h]
__device__ float  g_W2T[H * C];                 // W2^T [k][c]
__device__ float  g_last[B * H];                // h at t=len-1, original order
__device__ int    g_sidx[B];
__device__ int    g_slen[B];

// ---------------------------------------------------------------------------
// f32x2 helpers
// ---------------------------------------------------------------------------
typedef unsigned long long ull;
__device__ __forceinline__ ull pk2(float x, float y) {
    ull r; asm("mov.b64 %0, {%1, %2};" : "=l"(r) : "f"(x), "f"(y)); return r;
}
__device__ __forceinline__ void upk2(ull v, float& x, float& y) {
    asm("mov.b64 {%0, %1}, %2;" : "=f"(x), "=f"(y) : "l"(v));
}
__device__ __forceinline__ void fma2(ull& d, ull a, ull b) {
    asm("fma.rn.f32x2 %0, %1, %2, %3;" : "=l"(d) : "l"(a), "l"(b), "l"(d));
}
__device__ __forceinline__ void add2(ull& d, ull a, ull b) {
    asm("add.rn.f32x2 %0, %1, %2;" : "=l"(d) : "l"(a), "l"(b));
}

// ---------------------------------------------------------------------------
// Kernel 1: P[v][h] = sum_e emb[v,e] * W_ih[h,e] + b_ih[h] + b_hh[h]
// ---------------------------------------------------------------------------
__global__ void precompute_P(const float* __restrict__ emb,
                             const float* __restrict__ W_ih,
                             const float* __restrict__ b_ih,
                             const float* __restrict__ b_hh) {
    __shared__ float es[E];
    const int v = blockIdx.x;
    const int h = threadIdx.x;
    if (h < E) es[h] = emb[v * E + h];
    __syncthreads();

    float acc = b_ih[h] + b_hh[h];
    const float4* w  = reinterpret_cast<const float4*>(W_ih + h * E);
    const float4* e4 = reinterpret_cast<const float4*>(es);
#pragma unroll 8
    for (int i = 0; i < E / 4; i++) {
        float4 a = e4[i], b = w[i];
        acc += a.x * b.x + a.y * b.y + a.z * b.z + a.w * b.w;
    }
    g_P[v * H + h] = acc;
}

// ---------------------------------------------------------------------------
// Kernel 2: stable rank sort of rows by length
// ---------------------------------------------------------------------------
__global__ void sort_by_len(const int* __restrict__ lens) {
    __shared__ int sl[B];
    const int i = threadIdx.x;
    sl[i] = lens[i];
    __syncthreads();
    const int my = sl[i];
    int rank = 0;
#pragma unroll 8
    for (int j = 0; j < B; j++) {
        int lj = sl[j];
        rank += (lj < my) || (lj == my && j < i);
    }
    g_sidx[rank] = i;
    g_slen[rank] = my;
}

// ---------------------------------------------------------------------------
// Kernel 3: build paired-k W_hh layout + W1^T + W2^T
// g_Wp[kp*HPAIR+hp] = {W[2kp][2hp], W[2kp][2hp+1], W[2kp+1][2hp], W[2kp+1][2hp+1]}
// ---------------------------------------------------------------------------
__global__ void transpose_all(const float* __restrict__ W_hh,
                              const float* __restrict__ W1,
                              const float* __restrict__ W2) {
    int idx = blockIdx.x * blockDim.x + threadIdx.x;
    if (idx < H * H) {
        int h = idx >> 9, k = idx & (H - 1);
        int kp = k >> 1, hp = h >> 1;
        reinterpret_cast<float*>(g_Wp)[(kp * HPAIR + hp) * 4 + (k & 1) * 2 + (h & 1)]
            = W_hh[idx];
    } else if (idx < 2 * H * H) {
        int j = idx - H * H;
        int h = j >> 9, k = j & (H - 1);
        g_W1T[k * H + h] = W1[j];
    } else {
        int j = idx - 2 * H * H;
        if (j < C * H) {
            int c = j >> 9, k = j & (H - 1);
            g_W2T[k * C + c] = W2[j];
        }
    }
}

// ---------------------------------------------------------------------------
// Templated RNN inner compute: 4 kp (8 k), weights in regs.
// hT2 (ull view): [k][NB/2]  — pair p holds batches (2p, 2p+1).
// ---------------------------------------------------------------------------
template <int NB>
__device__ __forceinline__ void comp4T(const ull* __restrict__ hT2, int k0,
                                       const ulonglong2 w[4],
                                       ull* __restrict__ a0, ull* __restrict__ a1) {
#pragma unroll
    for (int j = 0; j < 4; j++) {
#pragma unroll
        for (int kk = 0; kk < 2; kk++) {
            const int k = k0 + 2 * j + kk;
            float wl, wh;
            upk2(kk ? w[j].y : w[j].x, wl, wh);
            ull s0 = pk2(wl, wl), s1 = pk2(wh, wh);
            const ulonglong2* hk =
                reinterpret_cast<const ulonglong2*>(hT2 + (unsigned)k * (NB / 2));
#pragma unroll
            for (int p = 0; p < NB / 4; p++) {
                ulonglong2 hv = hk[p];
                fma2(a0[2 * p], hv.x, s0); fma2(a0[2 * p + 1], hv.y, s0);
                fma2(a1[2 * p], hv.x, s1); fma2(a1[2 * p + 1], hv.y, s1);
            }
        }
    }
}

// ---------------------------------------------------------------------------
// Templated RNN body: NB batch rows, 4-way k-split, distributed epilogue.
// ---------------------------------------------------------------------------
template <int NB>
__device__ __forceinline__ void rnn_body(const int* __restrict__ x_in,
                                         int rowbase, char* smem) {
    constexpr int PBS = 4 * NB + 2;            // ull stride per hp row (16B-aligned)
    ull* hT2 = reinterpret_cast<ull*>(smem);                   // [512][NB/2]
    ull* pB  = hT2 + 512 * (NB / 2);                           // [256][PBS]
    int* ints = reinterpret_cast<int*>(pB + 256 * PBS);
    int* orig = ints;
    int* slen = ints + NB;
    int* xi   = ints + 2 * NB;

    const int tid = threadIdx.x;
    const int grp = tid >> 8;                  // 0..3
    const int hp  = tid & (HPAIR - 1);

    // epilogue role
    const int eh   = tid >> 1;                 // 0..511
    const int eq   = tid & 1;
    const int ehp  = eh >> 1;
    const int epar = eh & 1;

    if (tid < NB) {
        orig[tid] = g_sidx[rowbase + tid];
        slen[tid] = g_slen[rowbase + tid];
    }
    for (int i = tid; i < 512 * (NB / 2); i += THR) hT2[i] = 0ull;
    __syncthreads();

    int tmax = 0;
#pragma unroll
    for (int b = 0; b < NB; b++) tmax = max(tmax, slen[b]);

    const ulonglong2* Wp =
        reinterpret_cast<const ulonglong2*>(g_Wp) + (grp * 64) * HPAIR + hp;
    const int kbase = grp * 128;

    ull*       myPB = pB + hp * PBS + grp * NB;
    const ull* ePB  = pB + ehp * PBS + epar * (NB / 2) + eq * (NB / 4);

    for (int t = 0; t < tmax; t++) {
        if (tid < NB) xi[tid] = x_in[orig[tid] * S + t];
        __syncthreads();    // (1) xi ready; hT2 from previous epilogue visible

        // P prefetch for this thread's epilogue outputs (hidden behind GEMM)
        float pf[NB / 2];
#pragma unroll
        for (int i = 0; i < NB / 2; i++)
            pf[i] = __ldg(g_P + xi[eq * (NB / 2) + i] * H + eh);

        ull a0[NB / 2], a1[NB / 2];
#pragma unroll
        for (int p = 0; p < NB / 2; p++) { a0[p] = 0ull; a1[p] = 0ull; }

        // 64 kp for this group, 8-kp chunks, double-buffered W prefetch
        ulonglong2 wA[4], wB[4];
#pragma unroll
        for (int j = 0; j < 4; j++) wA[j] = __ldg(Wp + j * HPAIR);
#pragma unroll 1
        for (int c = 0; c < 64; c += 8) {
#pragma unroll
            for (int j = 0; j < 4; j++) wB[j] = __ldg(Wp + (c + 4 + j) * HPAIR);
            comp4T<NB>(hT2, kbase + 2 * c, wA, a0, a1);
            const int nc = (c + 8) & 63;       // wrap dummy on last iter
#pragma unroll
            for (int j = 0; j < 4; j++) wA[j] = __ldg(Wp + (nc + j) * HPAIR);
            comp4T<NB>(hT2, kbase + 2 * (c + 4), wB, a0, a1);
        }

        // write partials: a0 block then a1 block (aligned ulonglong2)
#pragma unroll
        for (int p = 0; p < NB / 2; p += 2)
            *reinterpret_cast<ulonglong2*>(myPB + p) =
                make_ulonglong2(a0[p], a0[p + 1]);
#pragma unroll
        for (int p = 0; p < NB / 2; p += 2)
            *reinterpret_cast<ulonglong2*>(myPB + NB / 2 + p) =
                make_ulonglong2(a1[p], a1[p + 1]);
        __syncthreads();    // (2) partials visible; all hT2 reads complete

        // distributed epilogue: thread = (h=eh, batches eq*NB/2 .. +NB/2)
        ull s[NB / 4];
#pragma unroll
        for (int q = 0; q < NB / 4; q++) s[q] = ePB[q];
#pragma unroll
        for (int g = 1; g < 4; g++) {
#pragma unroll
            for (int q = 0; q < NB / 4; q++) {
                ull v = ePB[g * NB + q];
                add2(s[q], s[q], v);
            }
        }
#pragma unroll
        for (int q = 0; q < NB / 4; q++)
            add2(s[q], s[q], pk2(pf[2 * q], pf[2 * q + 1]));

        float v[NB / 2];
#pragma unroll
        for (int q = 0; q < NB / 4; q++) {
            float x, y;
            upk2(s[q], x, y);
            v[2 * q]     = tanhf(x);
            v[2 * q + 1] = tanhf(y);
        }

        // state write back (pre-paired layout)
#pragma unroll
        for (int q = 0; q < NB / 4; q++)
            hT2[eh * (NB / 2) + eq * (NB / 4) + q] = pk2(v[2 * q], v[2 * q + 1]);

        // terminal-state stores
#pragma unroll
        for (int i = 0; i < NB / 2; i++) {
            const int b = eq * (NB / 2) + i;
            if (t == slen[b] - 1) g_last[orig[b] * H + eh] = v[i];
        }
        // next iteration's sync (1) orders hT2 writes before GEMM reads,
        // and pB reads above before next GEMM's pB writes.
    }
}

// ---------------------------------------------------------------------------
// Kernel 4: bucketed persistent RNN.
//   bid 0..85   : NB=4, rows 680 + 4*bid   (longest 344 rows, launched first)
//   bid 86..170 : NB=8, rows 672-8*(bid-86) (descending; shortest tiles last ->
//                 they are the overflow wave beyond 148 SMs)
// ---------------------------------------------------------------------------
__global__ void __launch_bounds__(THR, 1) rnn_kernel(const int* __restrict__ x_in) {
    extern __shared__ char smem[];
    const int bid = blockIdx.x;
    if (bid < N_CTA4) {
        rnn_body<4>(x_in, 680 + 4 * bid, smem);
    } else {
        rnn_body<8>(x_in, 672 - 8 * (bid - N_CTA4), smem);
    }
}

// ---------------------------------------------------------------------------
// MLP helpers (k-major W, unpaired)
// ---------------------------------------------------------------------------
#define HP (H / 2)
__device__ __forceinline__ void load8(const ull* __restrict__ WTu, int k, ull w[8]) {
#pragma unroll
    for (int j = 0; j < 8; j++) w[j] = __ldg(WTu + (unsigned)(k + j) * HP);
}
__device__ __forceinline__ void compute8(const ulonglong2* __restrict__ hT, int k0,
                                         const ull w[8], ull a0[BP], ull a1[BP]) {
#pragma unroll
    for (int j = 0; j < 8; j++) {
        ulonglong2 hA = hT[(k0 + j) * 2];
        ulonglong2 hB = hT[(k0 + j) * 2 + 1];
        float wl, wh;
        upk2(w[j], wl, wh);
        ull s0 = pk2(wl, wl), s1 = pk2(wh, wh);
        fma2(a0[0], hA.x, s0); fma2(a0[1], hA.y, s0);
        fma2(a0[2], hB.x, s0); fma2(a0[3], hB.y, s0);
        fma2(a1[0], hA.x, s1); fma2(a1[1], hA.y, s1);
        fma2(a1[2], hB.x, s1); fma2(a1[3], hB.y, s1);
    }
}
__device__ __forceinline__ void gemm_k512(const ull* __restrict__ WTu,
                                          const ulonglong2* __restrict__ hT,
                                          ull a0[BP], ull a1[BP]) {
    ull wA[8], wB[8];
    load8(WTu, 0, wA);
#pragma unroll 1
    for (int k0 = 0; k0 < H; k0 += 16) {
        load8(WTu, k0 + 8, wB);
        compute8(hT, k0, wA, a0, a1);
        int kn = (k0 + 16 < H) ? k0 + 16 : 0;
        load8(WTu, kn, wA);
        compute8(hT, k0 + 8, wB, a0, a1);
    }
}

// ---------------------------------------------------------------------------
// Kernel 5: MLP head
// ---------------------------------------------------------------------------
__global__ void __launch_bounds__(THRM) mlp_kernel(const float* __restrict__ b1,
                                                   const float* __restrict__ b2,
                                                   float* __restrict__ out) {
    __shared__ ulonglong2 hT[H * 2];
    __shared__ float hlin[BT * H];

    const int tid  = threadIdx.x;
    const int base = blockIdx.x * BT;

    float* hTf = reinterpret_cast<float*>(hT);
    for (int i = tid; i < BT * H; i += THRM) {
        int b = i >> 9, k = i & (H - 1);
        hTf[k * BT + b] = g_last[(base + b) * H + k];
    }
    __syncthreads();

    const ull* WTu = reinterpret_cast<const ull*>(g_W1T) + tid;

    float b1l = __ldg(b1 + 2 * tid), b1h = __ldg(b1 + 2 * tid + 1);
    ull a0[BP], a1[BP];
#pragma unroll
    for (int bp = 0; bp < BP; bp++) {
        a0[bp] = pk2(b1l, b1l);
        a1[bp] = pk2(b1h, b1h);
    }

    gemm_k512(WTu, hT, a0, a1);

#pragma unroll
    for (int bp = 0; bp < BP; bp++) {
        float x, y;
        upk2(a0[bp], x, y);
        float r0e = fmaxf(x, 0.f), r0o = fmaxf(y, 0.f);
        upk2(a1[bp], x, y);
        float r1e = fmaxf(x, 0.f), r1o = fmaxf(y, 0.f);
        reinterpret_cast<float2*>(hlin + (2 * bp) * H)[tid]     = make_float2(r0e, r1e);
        reinterpret_cast<float2*>(hlin + (2 * bp + 1) * H)[tid] = make_float2(r0o, r1o);
    }
    __syncthreads();

    const int b = tid >> 5;
    const int c = tid & 31;
    float acc = __ldg(b2 + c);
    const float* hb = hlin + b * H;
#pragma unroll 4
    for (int k = 0; k < H; k += 4) {
        float4 hv = *reinterpret_cast<const float4*>(hb + k);
        acc += hv.x * __ldg(g_W2T + (k + 0) * C + c);
        acc += hv.y * __ldg(g_W2T + (k + 1) * C + c);
        acc += hv.z * __ldg(g_W2T + (k + 2) * C + c);
        acc += hv.w * __ldg(g_W2T + (k + 3) * C + c);
    }
    out[(base + b) * C + c] = acc;
}

// ---------------------------------------------------------------------------
extern "C" void kernel_launch(void* const* d_in, const int* in_sizes, int n_in,
                              void* d_out, int out_size) {
    const int*   x_in   = (const int*)  d_in[0];
    const int*   x_lens = (const int*)  d_in[1];
    const float* emb    = (const float*)d_in[2];
    const float* W_ih   = (const float*)d_in[3];
    const float* b_ih   = (const float*)d_in[4];
    const float* W_hh   = (const float*)d_in[5];
    const float* b_hh   = (const float*)d_in[6];
    const float* W1w    = (const float*)d_in[7];
    const float* b1     = (const float*)d_in[8];
    const float* W2w    = (const float*)d_in[9];
    const float* b2     = (const float*)d_in[10];
    float* out = (float*)d_out;

    cudaFuncSetAttribute(rnn_kernel,
                         cudaFuncAttributeMaxDynamicSharedMemorySize, RNN_SMEM);

    precompute_P<<<V, H>>>(emb, W_ih, b_ih, b_hh);
    sort_by_len<<<1, B>>>(x_lens);
    int tgrid = (2 * H * H + C * H + 255) / 256;
    transpose_all<<<tgrid, 256>>>(W_hh, W1w, W2w);
    rnn_kernel<<<RNN_GRID, THR, RNN_SMEM>>>(x_in);
    mlp_kernel<<<B / BT, THRM>>>(b1, b2, out);
}

// round 7
// speedup vs baseline: 1.4469x; 1.0001x over previous
#include <cuda_runtime.h>
#include <math.h>

// Problem dims (fixed by the dataset)
#define B 1024
#define S 64
#define E 256
#define H 512
#define V 128
#define C 32

#define BT    8
#define HPAIR 256          // h-pairs
#define NGRP  4            // k-split groups
#define THR   (NGRP * 256) // 1024 threads

// bucketed rnn grid: 86 CTAs of 4 rows (longest) + 85 CTAs of 8 rows
#define N_CTA4  86
#define N_CTA8  85
#define RNN_GRID (N_CTA4 + N_CTA8)   // 171

// dynamic smem (worst case = NB=8): hT2 16384 + pB 256*34*8=69632 + ints
#define RNN_SMEM (16384 + 69632 + 96)

// mlp smem: hT2 16384 @0, pB 69632 @16384, hlin 16384 @86016, red 5120 @102400
#define MLP_HT2  0
#define MLP_PB   16384
#define MLP_HLIN 86016
#define MLP_RED  102400
#define MLP_SMEM (102400 + 5120)

// Scratch (no allocations allowed -> __device__ globals)
__device__ float  g_P[V * H];                   // emb @ W_ih^T + b_ih + b_hh
__device__ float4 g_Wp[(H / 2) * (H / 2)];      // paired W_hh^T (1 MB)
__device__ float4 g_W1p[(H / 2) * (H / 2)];     // paired W1^T   (1 MB)
__device__ float  g_W2T[H * C];                 // W2^T [k][c]
__device__ float  g_last[B * H];                // h at t=len-1, original order
__device__ int    g_sidx[B];
__device__ int    g_slen[B];

// ---------------------------------------------------------------------------
// f32x2 helpers
// ---------------------------------------------------------------------------
typedef unsigned long long ull;
__device__ __forceinline__ ull pk2(float x, float y) {
    ull r; asm("mov.b64 %0, {%1, %2};" : "=l"(r) : "f"(x), "f"(y)); return r;
}
__device__ __forceinline__ void upk2(ull v, float& x, float& y) {
    asm("mov.b64 {%0, %1}, %2;" : "=f"(x), "=f"(y) : "l"(v));
}
__device__ __forceinline__ void fma2(ull& d, ull a, ull b) {
    asm("fma.rn.f32x2 %0, %1, %2, %3;" : "=l"(d) : "l"(a), "l"(b), "l"(d));
}
__device__ __forceinline__ void add2(ull& d, ull a, ull b) {
    asm("add.rn.f32x2 %0, %1, %2;" : "=l"(d) : "l"(a), "l"(b));
}

// ---------------------------------------------------------------------------
// Kernel 1: P[v][h] = sum_e emb[v,e] * W_ih[h,e] + b_ih[h] + b_hh[h]
// ---------------------------------------------------------------------------
__global__ void precompute_P(const float* __restrict__ emb,
                             const float* __restrict__ W_ih,
                             const float* __restrict__ b_ih,
                             const float* __restrict__ b_hh) {
    __shared__ float es[E];
    const int v = blockIdx.x;
    const int h = threadIdx.x;
    if (h < E) es[h] = emb[v * E + h];
    __syncthreads();

    float acc = b_ih[h] + b_hh[h];
    const float4* w  = reinterpret_cast<const float4*>(W_ih + h * E);
    const float4* e4 = reinterpret_cast<const float4*>(es);
#pragma unroll 8
    for (int i = 0; i < E / 4; i++) {
        float4 a = e4[i], b = w[i];
        acc += a.x * b.x + a.y * b.y + a.z * b.z + a.w * b.w;
    }
    g_P[v * H + h] = acc;
}

// ---------------------------------------------------------------------------
// Kernel 2: stable rank sort of rows by length (16 blocks x 64 threads)
// ---------------------------------------------------------------------------
__global__ void sort_by_len(const int* __restrict__ lens) {
    const int i  = blockIdx.x * 64 + threadIdx.x;
    const int my = __ldg(lens + i);
    int rank = 0;
#pragma unroll 8
    for (int j = 0; j < B; j++) {
        int lj = __ldg(lens + j);
        rank += (lj < my) || (lj == my && j < i);
    }
    g_sidx[rank] = i;
    g_slen[rank] = my;
}

// ---------------------------------------------------------------------------
// Kernel 3: build paired-k layouts for W_hh and W1, plus W2^T
// g_Wp[kp*HPAIR+hp] = {W[2kp][2hp], W[2kp][2hp+1], W[2kp+1][2hp], W[2kp+1][2hp+1]}
// ---------------------------------------------------------------------------
__global__ void transpose_all(const float* __restrict__ W_hh,
                              const float* __restrict__ W1,
                              const float* __restrict__ W2) {
    int idx = blockIdx.x * blockDim.x + threadIdx.x;
    if (idx < H * H) {
        int h = idx >> 9, k = idx & (H - 1);
        int kp = k >> 1, hp = h >> 1;
        reinterpret_cast<float*>(g_Wp)[(kp * HPAIR + hp) * 4 + (k & 1) * 2 + (h & 1)]
            = W_hh[idx];
    } else if (idx < 2 * H * H) {
        int j = idx - H * H;
        int h = j >> 9, k = j & (H - 1);
        int kp = k >> 1, hp = h >> 1;
        reinterpret_cast<float*>(g_W1p)[(kp * HPAIR + hp) * 4 + (k & 1) * 2 + (h & 1)]
            = W1[j];
    } else {
        int j = idx - 2 * H * H;
        if (j < C * H) {
            int c = j >> 9, k = j & (H - 1);
            g_W2T[k * C + c] = W2[j];
        }
    }
}

// ---------------------------------------------------------------------------
// Inner compute: 2 kp (4 k) with weights in regs.
// hT2 (ull view): [k][NB/2] — pair p holds batches (2p, 2p+1).
// ---------------------------------------------------------------------------
template <int NB>
__device__ __forceinline__ void comp2T(const ull* __restrict__ hT2, int k0,
                                       const ulonglong2 w[2],
                                       ull* __restrict__ a0, ull* __restrict__ a1) {
#pragma unroll
    for (int j = 0; j < 2; j++) {
#pragma unroll
        for (int kk = 0; kk < 2; kk++) {
            const int k = k0 + 2 * j + kk;
            float wl, wh;
            upk2(kk ? w[j].y : w[j].x, wl, wh);
            ull s0 = pk2(wl, wl), s1 = pk2(wh, wh);
            const ulonglong2* hk =
                reinterpret_cast<const ulonglong2*>(hT2 + (unsigned)k * (NB / 2));
#pragma unroll
            for (int p = 0; p < NB / 4; p++) {
                ulonglong2 hv = hk[p];
                fma2(a0[2 * p], hv.x, s0); fma2(a0[2 * p + 1], hv.y, s0);
                fma2(a1[2 * p], hv.x, s1); fma2(a1[2 * p + 1], hv.y, s1);
            }
        }
    }
}

// 64-kp GEMM pass for one group: 4-buffer rotating prefetch (distance = 6 kp)
template <int NB>
__device__ __forceinline__ void gemm_group(const ulonglong2* __restrict__ Wp,
                                           const ull* __restrict__ hT2, int kbase,
                                           ull* __restrict__ a0, ull* __restrict__ a1) {
    ulonglong2 w0[2], w1[2], w2[2], w3[2];
#pragma unroll
    for (int j = 0; j < 2; j++) w0[j] = __ldg(Wp + (0 + j) * HPAIR);
#pragma unroll
    for (int j = 0; j < 2; j++) w1[j] = __ldg(Wp + (2 + j) * HPAIR);
#pragma unroll
    for (int j = 0; j < 2; j++) w2[j] = __ldg(Wp + (4 + j) * HPAIR);
#pragma unroll 1
    for (int c = 0; c < 64; c += 8) {
#pragma unroll
        for (int j = 0; j < 2; j++) w3[j] = __ldg(Wp + ((c + 6 + j) & 63) * HPAIR);
        comp2T<NB>(hT2, kbase + 2 * c, w0, a0, a1);
#pragma unroll
        for (int j = 0; j < 2; j++) w0[j] = __ldg(Wp + ((c + 8 + j) & 63) * HPAIR);
        comp2T<NB>(hT2, kbase + 2 * (c + 2), w1, a0, a1);
#pragma unroll
        for (int j = 0; j < 2; j++) w1[j] = __ldg(Wp + ((c + 10 + j) & 63) * HPAIR);
        comp2T<NB>(hT2, kbase + 2 * (c + 4), w2, a0, a1);
#pragma unroll
        for (int j = 0; j < 2; j++) w2[j] = __ldg(Wp + ((c + 12 + j) & 63) * HPAIR);
        comp2T<NB>(hT2, kbase + 2 * (c + 6), w3, a0, a1);
    }
}

// ---------------------------------------------------------------------------
// Templated RNN body: NB batch rows, 4-way k-split, distributed epilogue.
// ---------------------------------------------------------------------------
template <int NB>
__device__ __forceinline__ void rnn_body(const int* __restrict__ x_in,
                                         int rowbase, char* smem) {
    constexpr int PBS = 4 * NB + 2;            // ull stride per hp row
    ull* hT2 = reinterpret_cast<ull*>(smem);                   // [512][NB/2]
    ull* pB  = hT2 + 512 * (NB / 2);                           // [256][PBS]
    int* ints = reinterpret_cast<int*>(pB + 256 * PBS);
    int* orig = ints;
    int* slen = ints + NB;
    int* xi   = ints + 2 * NB;

    const int tid = threadIdx.x;
    const int grp = tid >> 8;                  // 0..3
    const int hp  = tid & (HPAIR - 1);

    // epilogue role
    const int eh   = tid >> 1;                 // 0..511
    const int eq   = tid & 1;
    const int ehp  = eh >> 1;
    const int epar = eh & 1;

    if (tid < NB) {
        orig[tid] = g_sidx[rowbase + tid];
        slen[tid] = g_slen[rowbase + tid];
    }
    for (int i = tid; i < 512 * (NB / 2); i += THR) hT2[i] = 0ull;
    __syncthreads();

    int tmax = 0;
#pragma unroll
    for (int b = 0; b < NB; b++) tmax = max(tmax, slen[b]);

    const ulonglong2* Wp =
        reinterpret_cast<const ulonglong2*>(g_Wp) + (grp * 64) * HPAIR + hp;
    const int kbase = grp * 128;

    ull*       myPB = pB + hp * PBS + grp * NB;
    const ull* ePB  = pB + ehp * PBS + epar * (NB / 2) + eq * (NB / 4);

    for (int t = 0; t < tmax; t++) {
        if (tid < NB) xi[tid] = x_in[orig[tid] * S + t];
        __syncthreads();    // (1) xi ready; hT2 from previous epilogue visible

        // P prefetch for this thread's epilogue outputs (hidden behind GEMM)
        float pf[NB / 2];
#pragma unroll
        for (int i = 0; i < NB / 2; i++)
            pf[i] = __ldg(g_P + xi[eq * (NB / 2) + i] * H + eh);

        ull a0[NB / 2], a1[NB / 2];
#pragma unroll
        for (int p = 0; p < NB / 2; p++) { a0[p] = 0ull; a1[p] = 0ull; }

        gemm_group<NB>(Wp, hT2, kbase, a0, a1);

        // write partials (aligned ulonglong2)
#pragma unroll
        for (int p = 0; p < NB / 2; p += 2)
            *reinterpret_cast<ulonglong2*>(myPB + p) =
                make_ulonglong2(a0[p], a0[p + 1]);
#pragma unroll
        for (int p = 0; p < NB / 2; p += 2)
            *reinterpret_cast<ulonglong2*>(myPB + NB / 2 + p) =
                make_ulonglong2(a1[p], a1[p + 1]);
        __syncthreads();    // (2) partials visible; all hT2 reads complete

        // distributed epilogue: thread = (h=eh, batches eq*NB/2 .. +NB/2)
        ull s[NB / 4];
#pragma unroll
        for (int q = 0; q < NB / 4; q++) s[q] = ePB[q];
#pragma unroll
        for (int g = 1; g < 4; g++) {
#pragma unroll
            for (int q = 0; q < NB / 4; q++) {
                ull v = ePB[g * NB + q];
                add2(s[q], s[q], v);
            }
        }
#pragma unroll
        for (int q = 0; q < NB / 4; q++)
            add2(s[q], s[q], pk2(pf[2 * q], pf[2 * q + 1]));

        float v[NB / 2];
#pragma unroll
        for (int q = 0; q < NB / 4; q++) {
            float x, y;
            upk2(s[q], x, y);
            v[2 * q]     = tanhf(x);
            v[2 * q + 1] = tanhf(y);
        }

        // state write back (pre-paired layout)
#pragma unroll
        for (int q = 0; q < NB / 4; q++)
            hT2[eh * (NB / 2) + eq * (NB / 4) + q] = pk2(v[2 * q], v[2 * q + 1]);

        // terminal-state stores
#pragma unroll
        for (int i = 0; i < NB / 2; i++) {
            const int b = eq * (NB / 2) + i;
            if (t == slen[b] - 1) g_last[orig[b] * H + eh] = v[i];
        }
    }
}

// ---------------------------------------------------------------------------
// Kernel 4: bucketed persistent RNN (same schedule as round 6)
// ---------------------------------------------------------------------------
__global__ void __launch_bounds__(THR, 1) rnn_kernel(const int* __restrict__ x_in) {
    extern __shared__ char smem[];
    const int bid = blockIdx.x;
    if (bid < N_CTA4) {
        rnn_body<4>(x_in, 680 + 4 * bid, smem);
    } else {
        rnn_body<8>(x_in, 672 - 8 * (bid - N_CTA4), smem);
    }
}

// ---------------------------------------------------------------------------
// Kernel 5: MLP head — one rnn-style NB=8 step (relu) + k-split logits.
// 1024 threads, 4-way k-split over W1 (paired layout).
// ---------------------------------------------------------------------------
__global__ void __launch_bounds__(THR, 1) mlp_kernel(const float* __restrict__ b1,
                                                     const float* __restrict__ b2,
                                                     float* __restrict__ out) {
    extern __shared__ char smem[];
    ull*   hT2  = reinterpret_cast<ull*>(smem + MLP_HT2);    // [512][4]
    ull*   pB   = reinterpret_cast<ull*>(smem + MLP_PB);     // [256][34]
    float* hlin = reinterpret_cast<float*>(smem + MLP_HLIN); // [8][512]
    float* red  = reinterpret_cast<float*>(smem + MLP_RED);  // [256][5]

    const int tid  = threadIdx.x;
    const int grp  = tid >> 8;
    const int hp   = tid & (HPAIR - 1);
    const int base = blockIdx.x * BT;

    const int eh   = tid >> 1;
    const int eq   = tid & 1;
    const int ehp  = eh >> 1;
    const int epar = eh & 1;

    // load 8 rows of g_last into paired [k][pair] layout
    hT2[eh * 4 + 2 * eq + 0] = pk2(g_last[(base + 4 * eq + 0) * H + eh],
                                   g_last[(base + 4 * eq + 1) * H + eh]);
    hT2[eh * 4 + 2 * eq + 1] = pk2(g_last[(base + 4 * eq + 2) * H + eh],
                                   g_last[(base + 4 * eq + 3) * H + eh]);
    __syncthreads();

    const ulonglong2* Wp =
        reinterpret_cast<const ulonglong2*>(g_W1p) + (grp * 64) * HPAIR + hp;

    ull a0[4], a1[4];
#pragma unroll
    for (int p = 0; p < 4; p++) { a0[p] = 0ull; a1[p] = 0ull; }

    gemm_group<8>(Wp, hT2, grp * 128, a0, a1);

    ull* myPB = pB + hp * 34 + grp * 8;
#pragma unroll
    for (int p = 0; p < 4; p += 2)
        *reinterpret_cast<ulonglong2*>(myPB + p) = make_ulonglong2(a0[p], a0[p + 1]);
#pragma unroll
    for (int p = 0; p < 4; p += 2)
        *reinterpret_cast<ulonglong2*>(myPB + 4 + p) = make_ulonglong2(a1[p], a1[p + 1]);
    __syncthreads();

    // distributed relu epilogue
    {
        const ull* ePB = pB + ehp * 34 + epar * 4 + eq * 2;
        ull s[2];
#pragma unroll
        for (int q = 0; q < 2; q++) s[q] = ePB[q];
#pragma unroll
        for (int g = 1; g < 4; g++) {
#pragma unroll
            for (int q = 0; q < 2; q++) {
                ull v = ePB[g * 8 + q];
                add2(s[q], s[q], v);
            }
        }
        const float bv = __ldg(b1 + eh);
#pragma unroll
        for (int q = 0; q < 2; q++) {
            float x, y;
            upk2(s[q], x, y);
            hlin[(eq * 4 + 2 * q + 0) * H + eh] = fmaxf(x + bv, 0.f);
            hlin[(eq * 4 + 2 * q + 1) * H + eh] = fmaxf(y + bv, 0.f);
        }
    }
    __syncthreads();

    // logits: thread (kq = tid>>8, b = (tid>>5)&7, c = tid&31), k-quarter each
    {
        const int kq = tid >> 8;
        const int r  = tid & 255;
        const int b  = r >> 5;
        const int c  = r & 31;
        float acc = 0.f;
        const float* hb = hlin + b * H + kq * 128;
        const float* w2 = g_W2T + (kq * 128) * C + c;
#pragma unroll 8
        for (int k = 0; k < 128; k++) acc += hb[k] * __ldg(w2 + k * C);
        red[r * 5 + kq] = acc;
    }
    __syncthreads();

    if (tid < 256) {
        const int b = tid >> 5, c = tid & 31;
        float acc = __ldg(b2 + c) + red[tid * 5 + 0] + red[tid * 5 + 1]
                  + red[tid * 5 + 2] + red[tid * 5 + 3];
        out[(base + b) * C + c] = acc;
    }
}

// ---------------------------------------------------------------------------
extern "C" void kernel_launch(void* const* d_in, const int* in_sizes, int n_in,
                              void* d_out, int out_size) {
    const int*   x_in   = (const int*)  d_in[0];
    const int*   x_lens = (const int*)  d_in[1];
    const float* emb    = (const float*)d_in[2];
    const float* W_ih   = (const float*)d_in[3];
    const float* b_ih   = (const float*)d_in[4];
    const float* W_hh   = (const float*)d_in[5];
    const float* b_hh   = (const float*)d_in[6];
    const float* W1w    = (const float*)d_in[7];
    const float* b1     = (const float*)d_in[8];
    const float* W2w    = (const float*)d_in[9];
    const float* b2     = (const float*)d_in[10];
    float* out = (float*)d_out;

    cudaFuncSetAttribute(rnn_kernel,
                         cudaFuncAttributeMaxDynamicSharedMemorySize, RNN_SMEM);
    cudaFuncSetAttribute(mlp_kernel,
                         cudaFuncAttributeMaxDynamicSharedMemorySize, MLP_SMEM);

    precompute_P<<<V, H>>>(emb, W_ih, b_ih, b_hh);
    sort_by_len<<<16, 64>>>(x_lens);
    int tgrid = (2 * H * H + C * H + 255) / 256;
    transpose_all<<<tgrid, 256>>>(W_hh, W1w, W2w);
    rnn_kernel<<<RNN_GRID, THR, RNN_SMEM>>>(x_in);
    mlp_kernel<<<B / BT, THR, MLP_SMEM>>>(b1, b2, out);
}

// round 8
// speedup vs baseline: 1.4838x; 1.0255x over previous
#include <cuda_runtime.h>
#include <math.h>

// Problem dims (fixed by the dataset)
#define B 1024
#define S 64
#define E 256
#define H 512
#define V 128
#define C 32

#define BT    8
#define HPAIR 256          // h-pairs
#define THR   1024

// buckets: NB4 CTAs (longest rows, 608..1023), NB8 CTAs (rows 0..607 desc)
#define N_CTA4  104
#define N_CTA8  76
#define RNN_GRID (N_CTA4 + N_CTA8)   // 180

// dynamic smem (both paths): 16384 (state) + 69632 (partials) + ints
#define RNN_SMEM (16384 + 69632 + 96)

// mlp smem layout (round-7)
#define MLP_HT2  0
#define MLP_PB   16384
#define MLP_HLIN 86016
#define MLP_RED  102400
#define MLP_SMEM (102400 + 5120)

// Scratch (no allocations allowed -> __device__ globals)
__device__ float  g_P[V * H];                   // emb @ W_ih^T + b_ih + b_hh
__device__ float4 g_Wp[(H / 2) * (H / 2)];      // paired W_hh^T (1 MB)
__device__ float4 g_W1p[(H / 2) * (H / 2)];     // paired W1^T   (1 MB)
__device__ float  g_W2T[H * C];                 // W2^T [k][c]
__device__ float  g_last[B * H];                // h at t=len-1, original order
__device__ int    g_sidx[B];
__device__ int    g_slen[B];

// ---------------------------------------------------------------------------
// f32x2 helpers
// ---------------------------------------------------------------------------
typedef unsigned long long ull;
__device__ __forceinline__ ull pk2(float x, float y) {
    ull r; asm("mov.b64 %0, {%1, %2};" : "=l"(r) : "f"(x), "f"(y)); return r;
}
__device__ __forceinline__ void upk2(ull v, float& x, float& y) {
    asm("mov.b64 {%0, %1}, %2;" : "=f"(x), "=f"(y) : "l"(v));
}
__device__ __forceinline__ void fma2(ull& d, ull a, ull b) {
    asm("fma.rn.f32x2 %0, %1, %2, %3;" : "=l"(d) : "l"(a), "l"(b), "l"(d));
}
__device__ __forceinline__ void add2(ull& d, ull a, ull b) {
    asm("add.rn.f32x2 %0, %1, %2;" : "=l"(d) : "l"(a), "l"(b));
}

// ---------------------------------------------------------------------------
// Kernel 1: P[v][h] = sum_e emb[v,e] * W_ih[h,e] + b_ih[h] + b_hh[h]
// ---------------------------------------------------------------------------
__global__ void precompute_P(const float* __restrict__ emb,
                             const float* __restrict__ W_ih,
                             const float* __restrict__ b_ih,
                             const float* __restrict__ b_hh) {
    __shared__ float es[E];
    const int v = blockIdx.x;
    const int h = threadIdx.x;
    if (h < E) es[h] = emb[v * E + h];
    __syncthreads();

    float acc = b_ih[h] + b_hh[h];
    const float4* w  = reinterpret_cast<const float4*>(W_ih + h * E);
    const float4* e4 = reinterpret_cast<const float4*>(es);
#pragma unroll 8
    for (int i = 0; i < E / 4; i++) {
        float4 a = e4[i], b = w[i];
        acc += a.x * b.x + a.y * b.y + a.z * b.z + a.w * b.w;
    }
    g_P[v * H + h] = acc;
}

// ---------------------------------------------------------------------------
// Kernel 2: stable rank sort of rows by length (16 blocks x 64 threads)
// ---------------------------------------------------------------------------
__global__ void sort_by_len(const int* __restrict__ lens) {
    const int i  = blockIdx.x * 64 + threadIdx.x;
    const int my = __ldg(lens + i);
    int rank = 0;
#pragma unroll 8
    for (int j = 0; j < B; j++) {
        int lj = __ldg(lens + j);
        rank += (lj < my) || (lj == my && j < i);
    }
    g_sidx[rank] = i;
    g_slen[rank] = my;
}

// ---------------------------------------------------------------------------
// Kernel 3: build paired-k layouts for W_hh and W1, plus W2^T
// g_Wp[kp*HPAIR+hp] = {W[2kp][2hp], W[2kp][2hp+1], W[2kp+1][2hp], W[2kp+1][2hp+1]}
// ---------------------------------------------------------------------------
__global__ void transpose_all(const float* __restrict__ W_hh,
                              const float* __restrict__ W1,
                              const float* __restrict__ W2) {
    int idx = blockIdx.x * blockDim.x + threadIdx.x;
    if (idx < H * H) {
        int h = idx >> 9, k = idx & (H - 1);
        int kp = k >> 1, hp = h >> 1;
        reinterpret_cast<float*>(g_Wp)[(kp * HPAIR + hp) * 4 + (k & 1) * 2 + (h & 1)]
            = W_hh[idx];
    } else if (idx < 2 * H * H) {
        int j = idx - H * H;
        int h = j >> 9, k = j & (H - 1);
        int kp = k >> 1, hp = h >> 1;
        reinterpret_cast<float*>(g_W1p)[(kp * HPAIR + hp) * 4 + (k & 1) * 2 + (h & 1)]
            = W1[j];
    } else {
        int j = idx - 2 * H * H;
        if (j < C * H) {
            int c = j >> 9, k = j & (H - 1);
            g_W2T[k * C + c] = W2[j];
        }
    }
}

// ---------------------------------------------------------------------------
// Round-6 packed-batch inner compute (NB8 + mlp): 4 kp (8 k), weights in regs.
// hT2 (ull view): [k][NB/2] — pair p holds batches (2p, 2p+1).
// ---------------------------------------------------------------------------
template <int NB>
__device__ __forceinline__ void comp4T(const ull* __restrict__ hT2, int k0,
                                       const ulonglong2 w[4],
                                       ull* __restrict__ a0, ull* __restrict__ a1) {
#pragma unroll
    for (int j = 0; j < 4; j++) {
#pragma unroll
        for (int kk = 0; kk < 2; kk++) {
            const int k = k0 + 2 * j + kk;
            float wl, wh;
            upk2(kk ? w[j].y : w[j].x, wl, wh);
            ull s0 = pk2(wl, wl), s1 = pk2(wh, wh);
            const ulonglong2* hk =
                reinterpret_cast<const ulonglong2*>(hT2 + (unsigned)k * (NB / 2));
#pragma unroll
            for (int p = 0; p < NB / 4; p++) {
                ulonglong2 hv = hk[p];
                fma2(a0[2 * p], hv.x, s0); fma2(a0[2 * p + 1], hv.y, s0);
                fma2(a1[2 * p], hv.x, s1); fma2(a1[2 * p + 1], hv.y, s1);
            }
        }
    }
}

// round-6 64-kp GEMM pass: 8-kp chunks, double-buffered W prefetch
template <int NB>
__device__ __forceinline__ void gemm_g6(const ulonglong2* __restrict__ Wp,
                                        const ull* __restrict__ hT2, int kbase,
                                        ull* __restrict__ a0, ull* __restrict__ a1) {
    ulonglong2 wA[4], wB[4];
#pragma unroll
    for (int j = 0; j < 4; j++) wA[j] = __ldg(Wp + j * HPAIR);
#pragma unroll 1
    for (int c = 0; c < 64; c += 8) {
#pragma unroll
        for (int j = 0; j < 4; j++) wB[j] = __ldg(Wp + (c + 4 + j) * HPAIR);
        comp4T<NB>(hT2, kbase + 2 * c, wA, a0, a1);
        const int nc = (c + 8) & 63;        // wrap dummy on last iter
#pragma unroll
        for (int j = 0; j < 4; j++) wA[j] = __ldg(Wp + (nc + j) * HPAIR);
        comp4T<NB>(hT2, kbase + 2 * (c + 4), wB, a0, a1);
    }
}

// ---------------------------------------------------------------------------
// NB=8 RNN body (round-6 proven version): 4-way k-split, packed-batch state.
// ---------------------------------------------------------------------------
__device__ __forceinline__ void rnn_body8(const int* __restrict__ x_in,
                                          int rowbase, char* smem) {
    constexpr int NB = 8;
    constexpr int PBS = 34;
    ull* hT2 = reinterpret_cast<ull*>(smem);                   // [512][4]
    ull* pB  = hT2 + 512 * 4;                                  // [256][34]
    int* ints = reinterpret_cast<int*>(pB + 256 * PBS);
    int* orig = ints;
    int* slen = ints + NB;
    int* xi   = ints + 2 * NB;

    const int tid = threadIdx.x;
    const int grp = tid >> 8;
    const int hp  = tid & (HPAIR - 1);

    const int eh   = tid >> 1;
    const int eq   = tid & 1;
    const int ehp  = eh >> 1;
    const int epar = eh & 1;

    if (tid < NB) {
        orig[tid] = g_sidx[rowbase + tid];
        slen[tid] = g_slen[rowbase + tid];
    }
    for (int i = tid; i < 512 * 4; i += THR) hT2[i] = 0ull;
    __syncthreads();

    int tmax = 0;
#pragma unroll
    for (int b = 0; b < NB; b++) tmax = max(tmax, slen[b]);

    const ulonglong2* Wp =
        reinterpret_cast<const ulonglong2*>(g_Wp) + (grp * 64) * HPAIR + hp;
    const int kbase = grp * 128;

    ull*       myPB = pB + hp * PBS + grp * NB;
    const ull* ePB  = pB + ehp * PBS + epar * 4 + eq * 2;

    for (int t = 0; t < tmax; t++) {
        if (tid < NB) xi[tid] = x_in[orig[tid] * S + t];
        __syncthreads();

        float pf[4];
#pragma unroll
        for (int i = 0; i < 4; i++)
            pf[i] = __ldg(g_P + xi[eq * 4 + i] * H + eh);

        ull a0[4], a1[4];
#pragma unroll
        for (int p = 0; p < 4; p++) { a0[p] = 0ull; a1[p] = 0ull; }

        gemm_g6<8>(Wp, hT2, kbase, a0, a1);

#pragma unroll
        for (int p = 0; p < 4; p += 2)
            *reinterpret_cast<ulonglong2*>(myPB + p) =
                make_ulonglong2(a0[p], a0[p + 1]);
#pragma unroll
        for (int p = 0; p < 4; p += 2)
            *reinterpret_cast<ulonglong2*>(myPB + 4 + p) =
                make_ulonglong2(a1[p], a1[p + 1]);
        __syncthreads();

        ull s[2];
#pragma unroll
        for (int q = 0; q < 2; q++) s[q] = ePB[q];
#pragma unroll
        for (int g = 1; g < 4; g++) {
#pragma unroll
            for (int q = 0; q < 2; q++) {
                ull v = ePB[g * NB + q];
                add2(s[q], s[q], v);
            }
        }
#pragma unroll
        for (int q = 0; q < 2; q++)
            add2(s[q], s[q], pk2(pf[2 * q], pf[2 * q + 1]));

        float v[4];
#pragma unroll
        for (int q = 0; q < 2; q++) {
            float x, y;
            upk2(s[q], x, y);
            v[2 * q]     = tanhf(x);
            v[2 * q + 1] = tanhf(y);
        }
#pragma unroll
        for (int q = 0; q < 2; q++)
            hT2[eh * 4 + eq * 2 + q] = pk2(v[2 * q], v[2 * q + 1]);

#pragma unroll
        for (int i = 0; i < 4; i++) {
            const int b = eq * 4 + i;
            if (t == slen[b] - 1) g_last[orig[b] * H + eh] = v[i];
        }
    }
}

// ---------------------------------------------------------------------------
// NB=4 RNN body — MOV-free inner loop.
// 8-way k-split; thread owns h-pairs hp0 = tid&127 and hp1 = hp0+128.
// State hd[k][b] stores DUPLICATED values pk2(h,h) so both FFMA2 operands are
// load-native: acc(h0,h1 | b) += W_pair_ull * hDup_ull.  Zero splat MOVs.
// ---------------------------------------------------------------------------
__device__ __forceinline__ void rnn_body4(const int* __restrict__ x_in,
                                          int rowbase, char* smem) {
    ull* hd = reinterpret_cast<ull*>(smem);                    // [512][4]
    ull* pB = hd + 512 * 4;                                    // [256][34]
    int* ints = reinterpret_cast<int*>(pB + 256 * 34);
    int* orig = ints;
    int* slen = ints + 4;
    int* xi   = ints + 8;

    const int tid = threadIdx.x;
    const int grp = tid >> 7;              // 0..7
    const int u   = tid & 127;
    const int hp0 = u;
    const int hp1 = u + 128;

    // epilogue role: thread = (h-pair ehp, batch eb)
    const int ehp = tid >> 2;              // 0..255
    const int eb  = tid & 3;

    if (tid < 4) {
        orig[tid] = g_sidx[rowbase + tid];
        slen[tid] = g_slen[rowbase + tid];
    }
    for (int i = tid; i < 512 * 4; i += THR) hd[i] = 0ull;
    __syncthreads();

    int tmax = 0;
#pragma unroll
    for (int b = 0; b < 4; b++) tmax = max(tmax, slen[b]);

    const ulonglong2* Wb = reinterpret_cast<const ulonglong2*>(g_Wp);
    const int kb = grp * 32;               // kp base for this group

    ull*       wr0 = pB + hp0 * 34 + grp * 4;
    ull*       wr1 = pB + hp1 * 34 + grp * 4;
    const ull* rd  = pB + ehp * 34 + eb;

    for (int t = 0; t < tmax; t++) {
        if (tid < 4) xi[tid] = x_in[orig[tid] * S + t];
        __syncthreads();    // (1) xi ready; hd from previous epilogue visible

        // epilogue P prefetch: (P[xi[eb]][2ehp], P[xi[eb]][2ehp+1])
        float2 pf = __ldg(reinterpret_cast<const float2*>(g_P + xi[eb] * H) + ehp);

        ull a0[4], a1[4];
#pragma unroll
        for (int b = 0; b < 4; b++) { a0[b] = 0ull; a1[b] = 0ull; }

        // 32 kp, 2-kp unrolled, double-buffered W prefetch
        ulonglong2 wa0 = __ldg(Wb + (kb + 0) * HPAIR + hp0);
        ulonglong2 wa1 = __ldg(Wb + (kb + 0) * HPAIR + hp1);
        ulonglong2 wc0 = __ldg(Wb + (kb + 1) * HPAIR + hp0);
        ulonglong2 wc1 = __ldg(Wb + (kb + 1) * HPAIR + hp1);
#pragma unroll 4
        for (int c = 0; c < 32; c += 2) {
            const int n0 = (c + 2) & 31;
            const int n1 = (c + 3) & 31;
            ulonglong2 wb0 = __ldg(Wb + (kb + n0) * HPAIR + hp0);
            ulonglong2 wb1 = __ldg(Wb + (kb + n0) * HPAIR + hp1);
            {
                const ull* hk = hd + (unsigned)(2 * (kb + c)) * 4;
                ulonglong2 hA = *reinterpret_cast<const ulonglong2*>(hk);     // k even: b0,b1
                ulonglong2 hB = *reinterpret_cast<const ulonglong2*>(hk + 2); // b2,b3
                fma2(a0[0], wa0.x, hA.x); fma2(a0[1], wa0.x, hA.y);
                fma2(a0[2], wa0.x, hB.x); fma2(a0[3], wa0.x, hB.y);
                fma2(a1[0], wa1.x, hA.x); fma2(a1[1], wa1.x, hA.y);
                fma2(a1[2], wa1.x, hB.x); fma2(a1[3], wa1.x, hB.y);
                hA = *reinterpret_cast<const ulonglong2*>(hk + 4);            // k odd
                hB = *reinterpret_cast<const ulonglong2*>(hk + 6);
                fma2(a0[0], wa0.y, hA.x); fma2(a0[1], wa0.y, hA.y);
                fma2(a0[2], wa0.y, hB.x); fma2(a0[3], wa0.y, hB.y);
                fma2(a1[0], wa1.y, hA.x); fma2(a1[1], wa1.y, hA.y);
                fma2(a1[2], wa1.y, hB.x); fma2(a1[3], wa1.y, hB.y);
            }
            ulonglong2 wd0 = __ldg(Wb + (kb + n1) * HPAIR + hp0);
            ulonglong2 wd1 = __ldg(Wb + (kb + n1) * HPAIR + hp1);
            {
                const ull* hk = hd + (unsigned)(2 * (kb + c + 1)) * 4;
                ulonglong2 hA = *reinterpret_cast<const ulonglong2*>(hk);
                ulonglong2 hB = *reinterpret_cast<const ulonglong2*>(hk + 2);
                fma2(a0[0], wc0.x, hA.x); fma2(a0[1], wc0.x, hA.y);
                fma2(a0[2], wc0.x, hB.x); fma2(a0[3], wc0.x, hB.y);
                fma2(a1[0], wc1.x, hA.x); fma2(a1[1], wc1.x, hA.y);
                fma2(a1[2], wc1.x, hB.x); fma2(a1[3], wc1.x, hB.y);
                hA = *reinterpret_cast<const ulonglong2*>(hk + 4);
                hB = *reinterpret_cast<const ulonglong2*>(hk + 6);
                fma2(a0[0], wc0.y, hA.x); fma2(a0[1], wc0.y, hA.y);
                fma2(a0[2], wc0.y, hB.x); fma2(a0[3], wc0.y, hB.y);
                fma2(a1[0], wc1.y, hA.x); fma2(a1[1], wc1.y, hA.y);
                fma2(a1[2], wc1.y, hB.x); fma2(a1[3], wc1.y, hB.y);
            }
            wa0 = wb0; wa1 = wb1; wc0 = wd0; wc1 = wd1;
        }

        // write partials: pB[hp][grp][b]
        *reinterpret_cast<ulonglong2*>(wr0)     = make_ulonglong2(a0[0], a0[1]);
        *reinterpret_cast<ulonglong2*>(wr0 + 2) = make_ulonglong2(a0[2], a0[3]);
        *reinterpret_cast<ulonglong2*>(wr1)     = make_ulonglong2(a1[0], a1[1]);
        *reinterpret_cast<ulonglong2*>(wr1 + 2) = make_ulonglong2(a1[2], a1[3]);
        __syncthreads();    // (2) partials visible; all hd reads complete

        // distributed epilogue: (h-pair ehp, batch eb)
        ull s = rd[0];
#pragma unroll
        for (int g = 1; g < 8; g++) {
            ull v = rd[g * 4];
            add2(s, s, v);
        }
        add2(s, s, pk2(pf.x, pf.y));

        float x0, x1;
        upk2(s, x0, x1);
        const float v0 = tanhf(x0);
        const float v1 = tanhf(x1);

        // duplicated state write
        hd[(2 * ehp) * 4 + eb]     = pk2(v0, v0);
        hd[(2 * ehp + 1) * 4 + eb] = pk2(v1, v1);

        if (t == slen[eb] - 1)
            *reinterpret_cast<float2*>(g_last + orig[eb] * H + 2 * ehp) =
                make_float2(v0, v1);
    }
}

// ---------------------------------------------------------------------------
// Kernel 4: bucketed persistent RNN.
//   bid 0..103   : NB=4, rows 608 + 4*bid (longest 416 rows)
//   bid 104..179 : NB=8, rows 600 - 8*(bid-104) (descending; shortest last)
// ---------------------------------------------------------------------------
__global__ void __launch_bounds__(THR, 1) rnn_kernel(const int* __restrict__ x_in) {
    extern __shared__ char smem[];
    const int bid = blockIdx.x;
    if (bid < N_CTA4) {
        rnn_body4(x_in, 608 + 4 * bid, smem);
    } else {
        rnn_body8(x_in, 600 - 8 * (bid - N_CTA4), smem);
    }
}

// ---------------------------------------------------------------------------
// Kernel 5: MLP head — one rnn-style NB=8 step (relu) + k-split logits.
// ---------------------------------------------------------------------------
__global__ void __launch_bounds__(THR, 1) mlp_kernel(const float* __restrict__ b1,
                                                     const float* __restrict__ b2,
                                                     float* __restrict__ out) {
    extern __shared__ char smem[];
    ull*   hT2  = reinterpret_cast<ull*>(smem + MLP_HT2);    // [512][4]
    ull*   pB   = reinterpret_cast<ull*>(smem + MLP_PB);     // [256][34]
    float* hlin = reinterpret_cast<float*>(smem + MLP_HLIN); // [8][512]
    float* red  = reinterpret_cast<float*>(smem + MLP_RED);  // [256][5]

    const int tid  = threadIdx.x;
    const int grp  = tid >> 8;
    const int hp   = tid & (HPAIR - 1);
    const int base = blockIdx.x * BT;

    const int eh   = tid >> 1;
    const int eq   = tid & 1;
    const int ehp  = eh >> 1;
    const int epar = eh & 1;

    hT2[eh * 4 + 2 * eq + 0] = pk2(g_last[(base + 4 * eq + 0) * H + eh],
                                   g_last[(base + 4 * eq + 1) * H + eh]);
    hT2[eh * 4 + 2 * eq + 1] = pk2(g_last[(base + 4 * eq + 2) * H + eh],
                                   g_last[(base + 4 * eq + 3) * H + eh]);
    __syncthreads();

    const ulonglong2* Wp =
        reinterpret_cast<const ulonglong2*>(g_W1p) + (grp * 64) * HPAIR + hp;

    ull a0[4], a1[4];
#pragma unroll
    for (int p = 0; p < 4; p++) { a0[p] = 0ull; a1[p] = 0ull; }

    gemm_g6<8>(Wp, hT2, grp * 128, a0, a1);

    ull* myPB = pB + hp * 34 + grp * 8;
#pragma unroll
    for (int p = 0; p < 4; p += 2)
        *reinterpret_cast<ulonglong2*>(myPB + p) = make_ulonglong2(a0[p], a0[p + 1]);
#pragma unroll
    for (int p = 0; p < 4; p += 2)
        *reinterpret_cast<ulonglong2*>(myPB + 4 + p) = make_ulonglong2(a1[p], a1[p + 1]);
    __syncthreads();

    {
        const ull* ePB = pB + ehp * 34 + epar * 4 + eq * 2;
        ull s[2];
#pragma unroll
        for (int q = 0; q < 2; q++) s[q] = ePB[q];
#pragma unroll
        for (int g = 1; g < 4; g++) {
#pragma unroll
            for (int q = 0; q < 2; q++) {
                ull v = ePB[g * 8 + q];
                add2(s[q], s[q], v);
            }
        }
        const float bv = __ldg(b1 + eh);
#pragma unroll
        for (int q = 0; q < 2; q++) {
            float x, y;
            upk2(s[q], x, y);
            hlin[(eq * 4 + 2 * q + 0) * H + eh] = fmaxf(x + bv, 0.f);
            hlin[(eq * 4 + 2 * q + 1) * H + eh] = fmaxf(y + bv, 0.f);
        }
    }
    __syncthreads();

    {
        const int kq = tid >> 8;
        const int r  = tid & 255;
        const int b  = r >> 5;
        const int c  = r & 31;
        float acc = 0.f;
        const float* hb = hlin + b * H + kq * 128;
        const float* w2 = g_W2T + (kq * 128) * C + c;
#pragma unroll 8
        for (int k = 0; k < 128; k++) acc += hb[k] * __ldg(w2 + k * C);
        red[r * 5 + kq] = acc;
    }
    __syncthreads();

    if (tid < 256) {
        const int b = tid >> 5, c = tid & 31;
        float acc = __ldg(b2 + c) + red[tid * 5 + 0] + red[tid * 5 + 1]
                  + red[tid * 5 + 2] + red[tid * 5 + 3];
        out[(base + b) * C + c] = acc;
    }
}

// ---------------------------------------------------------------------------
extern "C" void kernel_launch(void* const* d_in, const int* in_sizes, int n_in,
                              void* d_out, int out_size) {
    const int*   x_in   = (const int*)  d_in[0];
    const int*   x_lens = (const int*)  d_in[1];
    const float* emb    = (const float*)d_in[2];
    const float* W_ih   = (const float*)d_in[3];
    const float* b_ih   = (const float*)d_in[4];
    const float* W_hh   = (const float*)d_in[5];
    const float* b_hh   = (const float*)d_in[6];
    const float* W1w    = (const float*)d_in[7];
    const float* b1     = (const float*)d_in[8];
    const float* W2w    = (const float*)d_in[9];
    const float* b2     = (const float*)d_in[10];
    float* out = (float*)d_out;

    cudaFuncSetAttribute(rnn_kernel,
                         cudaFuncAttributeMaxDynamicSharedMemorySize, RNN_SMEM);
    cudaFuncSetAttribute(mlp_kernel,
                         cudaFuncAttributeMaxDynamicSharedMemorySize, MLP_SMEM);

    precompute_P<<<V, H>>>(emb, W_ih, b_ih, b_hh);
    sort_by_len<<<16, 64>>>(x_lens);
    int tgrid = (2 * H * H + C * H + 255) / 256;
    transpose_all<<<tgrid, 256>>>(W_hh, W1w, W2w);
    rnn_kernel<<<RNN_GRID, THR, RNN_SMEM>>>(x_in);
    mlp_kernel<<<B / BT, THR, MLP_SMEM>>>(b1, b2, out);
}

// round 9
// speedup vs baseline: 1.6690x; 1.1248x over previous
#include <cuda_runtime.h>
#include <math.h>

// Problem dims (fixed by the dataset)
#define B 1024
#define S 64
#define E 256
#define H 512
#define V 128
#define C 32

#define BT    8
#define HPAIR 256          // h-pairs
#define THR   1024

// buckets: NB4 CTAs (longest rows, 608..1023), NB8 CTAs (rows 0..607 desc)
#define N_CTA4  104
#define N_CTA8  76
#define RNN_GRID (N_CTA4 + N_CTA8)   // 180

// dynamic smem (worst case = NB8 path): 16384 (state) + 69632 (partials) + ints
#define RNN_SMEM (16384 + 69632 + 96)

// mlp smem layout
#define MLP_HT2  0
#define MLP_PB   16384
#define MLP_HLIN 86016
#define MLP_RED  102400
#define MLP_SMEM (102400 + 5120)

// Scratch (no allocations allowed -> __device__ globals)
__device__ float  g_P[V * H];                   // emb @ W_ih^T + b_ih + b_hh
__device__ float4 g_Wp[(H / 2) * (H / 2)];      // paired W_hh^T (1 MB)
__device__ float4 g_W1p[(H / 2) * (H / 2)];     // paired W1^T   (1 MB)
__device__ float  g_W2T[H * C];                 // W2^T [k][c]
__device__ float  g_last[B * H];                // h at t=len-1, original order
__device__ int    g_sidx[B];
__device__ int    g_slen[B];

// ---------------------------------------------------------------------------
// f32x2 helpers
// ---------------------------------------------------------------------------
typedef unsigned long long ull;
__device__ __forceinline__ ull pk2(float x, float y) {
    ull r; asm("mov.b64 %0, {%1, %2};" : "=l"(r) : "f"(x), "f"(y)); return r;
}
__device__ __forceinline__ void upk2(ull v, float& x, float& y) {
    asm("mov.b64 {%0, %1}, %2;" : "=f"(x), "=f"(y) : "l"(v));
}
__device__ __forceinline__ void fma2(ull& d, ull a, ull b) {
    asm("fma.rn.f32x2 %0, %1, %2, %3;" : "=l"(d) : "l"(a), "l"(b), "l"(d));
}
__device__ __forceinline__ void add2(ull& d, ull a, ull b) {
    asm("add.rn.f32x2 %0, %1, %2;" : "=l"(d) : "l"(a), "l"(b));
}

// ---------------------------------------------------------------------------
// Kernel 1: P[v][h] = sum_e emb[v,e] * W_ih[h,e] + b_ih[h] + b_hh[h]
// ---------------------------------------------------------------------------
__global__ void precompute_P(const float* __restrict__ emb,
                             const float* __restrict__ W_ih,
                             const float* __restrict__ b_ih,
                             const float* __restrict__ b_hh) {
    __shared__ float es[E];
    const int v = blockIdx.x;
    const int h = threadIdx.x;
    if (h < E) es[h] = emb[v * E + h];
    __syncthreads();

    float acc = b_ih[h] + b_hh[h];
    const float4* w  = reinterpret_cast<const float4*>(W_ih + h * E);
    const float4* e4 = reinterpret_cast<const float4*>(es);
#pragma unroll 8
    for (int i = 0; i < E / 4; i++) {
        float4 a = e4[i], b = w[i];
        acc += a.x * b.x + a.y * b.y + a.z * b.z + a.w * b.w;
    }
    g_P[v * H + h] = acc;
}

// ---------------------------------------------------------------------------
// Kernel 2: stable rank sort of rows by length (16 blocks x 64 threads)
// ---------------------------------------------------------------------------
__global__ void sort_by_len(const int* __restrict__ lens) {
    const int i  = blockIdx.x * 64 + threadIdx.x;
    const int my = __ldg(lens + i);
    int rank = 0;
#pragma unroll 8
    for (int j = 0; j < B; j++) {
        int lj = __ldg(lens + j);
        rank += (lj < my) || (lj == my && j < i);
    }
    g_sidx[rank] = i;
    g_slen[rank] = my;
}

// ---------------------------------------------------------------------------
// Kernel 3: build paired-k layouts for W_hh and W1, plus W2^T
// g_Wp[kp*HPAIR+hp] = {W[2kp][2hp], W[2kp][2hp+1], W[2kp+1][2hp], W[2kp+1][2hp+1]}
// ---------------------------------------------------------------------------
__global__ void transpose_all(const float* __restrict__ W_hh,
                              const float* __restrict__ W1,
                              const float* __restrict__ W2) {
    int idx = blockIdx.x * blockDim.x + threadIdx.x;
    if (idx < H * H) {
        int h = idx >> 9, k = idx & (H - 1);
        int kp = k >> 1, hp = h >> 1;
        reinterpret_cast<float*>(g_Wp)[(kp * HPAIR + hp) * 4 + (k & 1) * 2 + (h & 1)]
            = W_hh[idx];
    } else if (idx < 2 * H * H) {
        int j = idx - H * H;
        int h = j >> 9, k = j & (H - 1);
        int kp = k >> 1, hp = h >> 1;
        reinterpret_cast<float*>(g_W1p)[(kp * HPAIR + hp) * 4 + (k & 1) * 2 + (h & 1)]
            = W1[j];
    } else {
        int j = idx - 2 * H * H;
        if (j < C * H) {
            int c = j >> 9, k = j & (H - 1);
            g_W2T[k * C + c] = W2[j];
        }
    }
}

// ---------------------------------------------------------------------------
// Packed-batch inner compute (NB8 + mlp): 4 kp (8 k), weights in regs.
// hT2 (ull view): [k][NB/2] — pair p holds batches (2p, 2p+1).
// ---------------------------------------------------------------------------
template <int NB>
__device__ __forceinline__ void comp4T(const ull* __restrict__ hT2, int k0,
                                       const ulonglong2 w[4],
                                       ull* __restrict__ a0, ull* __restrict__ a1) {
#pragma unroll
    for (int j = 0; j < 4; j++) {
#pragma unroll
        for (int kk = 0; kk < 2; kk++) {
            const int k = k0 + 2 * j + kk;
            float wl, wh;
            upk2(kk ? w[j].y : w[j].x, wl, wh);
            ull s0 = pk2(wl, wl), s1 = pk2(wh, wh);
            const ulonglong2* hk =
                reinterpret_cast<const ulonglong2*>(hT2 + (unsigned)k * (NB / 2));
#pragma unroll
            for (int p = 0; p < NB / 4; p++) {
                ulonglong2 hv = hk[p];
                fma2(a0[2 * p], hv.x, s0); fma2(a0[2 * p + 1], hv.y, s0);
                fma2(a1[2 * p], hv.x, s1); fma2(a1[2 * p + 1], hv.y, s1);
            }
        }
    }
}

// 64-kp GEMM pass: 8-kp chunks, double-buffered W prefetch
template <int NB>
__device__ __forceinline__ void gemm_g6(const ulonglong2* __restrict__ Wp,
                                        const ull* __restrict__ hT2, int kbase,
                                        ull* __restrict__ a0, ull* __restrict__ a1) {
    ulonglong2 wA[4], wB[4];
#pragma unroll
    for (int j = 0; j < 4; j++) wA[j] = __ldg(Wp + j * HPAIR);
#pragma unroll 1
    for (int c = 0; c < 64; c += 8) {
#pragma unroll
        for (int j = 0; j < 4; j++) wB[j] = __ldg(Wp + (c + 4 + j) * HPAIR);
        comp4T<NB>(hT2, kbase + 2 * c, wA, a0, a1);
        const int nc = (c + 8) & 63;        // wrap dummy on last iter
#pragma unroll
        for (int j = 0; j < 4; j++) wA[j] = __ldg(Wp + (nc + j) * HPAIR);
        comp4T<NB>(hT2, kbase + 2 * (c + 4), wB, a0, a1);
    }
}

// ---------------------------------------------------------------------------
// NB=8 RNN body (proven round-6 version): 4-way k-split, packed-batch state.
// ---------------------------------------------------------------------------
__device__ __forceinline__ void rnn_body8(const int* __restrict__ x_in,
                                          int rowbase, char* smem) {
    constexpr int NB = 8;
    constexpr int PBS = 34;
    ull* hT2 = reinterpret_cast<ull*>(smem);                   // [512][4]
    ull* pB  = hT2 + 512 * 4;                                  // [256][34]
    int* ints = reinterpret_cast<int*>(pB + 256 * PBS);
    int* orig = ints;
    int* slen = ints + NB;
    int* xi   = ints + 2 * NB;

    const int tid = threadIdx.x;
    const int grp = tid >> 8;
    const int hp  = tid & (HPAIR - 1);

    const int eh   = tid >> 1;
    const int eq   = tid & 1;
    const int ehp  = eh >> 1;
    const int epar = eh & 1;

    if (tid < NB) {
        orig[tid] = g_sidx[rowbase + tid];
        slen[tid] = g_slen[rowbase + tid];
    }
    for (int i = tid; i < 512 * 4; i += THR) hT2[i] = 0ull;
    __syncthreads();

    int tmax = 0;
#pragma unroll
    for (int b = 0; b < NB; b++) tmax = max(tmax, slen[b]);

    const ulonglong2* Wp =
        reinterpret_cast<const ulonglong2*>(g_Wp) + (grp * 64) * HPAIR + hp;
    const int kbase = grp * 128;

    ull*       myPB = pB + hp * PBS + grp * NB;
    const ull* ePB  = pB + ehp * PBS + epar * 4 + eq * 2;

    for (int t = 0; t < tmax; t++) {
        if (tid < NB) xi[tid] = x_in[orig[tid] * S + t];
        __syncthreads();

        float pf[4];
#pragma unroll
        for (int i = 0; i < 4; i++)
            pf[i] = __ldg(g_P + xi[eq * 4 + i] * H + eh);

        ull a0[4], a1[4];
#pragma unroll
        for (int p = 0; p < 4; p++) { a0[p] = 0ull; a1[p] = 0ull; }

        gemm_g6<8>(Wp, hT2, kbase, a0, a1);

#pragma unroll
        for (int p = 0; p < 4; p += 2)
            *reinterpret_cast<ulonglong2*>(myPB + p) =
                make_ulonglong2(a0[p], a0[p + 1]);
#pragma unroll
        for (int p = 0; p < 4; p += 2)
            *reinterpret_cast<ulonglong2*>(myPB + 4 + p) =
                make_ulonglong2(a1[p], a1[p + 1]);
        __syncthreads();

        ull s[2];
#pragma unroll
        for (int q = 0; q < 2; q++) s[q] = ePB[q];
#pragma unroll
        for (int g = 1; g < 4; g++) {
#pragma unroll
            for (int q = 0; q < 2; q++) {
                ull v = ePB[g * NB + q];
                add2(s[q], s[q], v);
            }
        }
#pragma unroll
        for (int q = 0; q < 2; q++)
            add2(s[q], s[q], pk2(pf[2 * q], pf[2 * q + 1]));

        float v[4];
#pragma unroll
        for (int q = 0; q < 2; q++) {
            float x, y;
            upk2(s[q], x, y);
            v[2 * q]     = tanhf(x);
            v[2 * q + 1] = tanhf(y);
        }
#pragma unroll
        for (int q = 0; q < 2; q++)
            hT2[eh * 4 + eq * 2 + q] = pk2(v[2 * q], v[2 * q + 1]);

#pragma unroll
        for (int i = 0; i < 4; i++) {
            const int b = eq * 4 + i;
            if (t == slen[b] - 1) g_last[orig[b] * H + eh] = v[i];
        }
    }
}

// ---------------------------------------------------------------------------
// NB=4 RNN body — non-duplicated state, minimal LDS traffic.
// 8-way k-split; thread owns h-pairs hp0 = tid&127 and hp1 = hp0+128.
// State hd[kp][b] = float2(h[2kp], h[2kp+1])  (8 B per (kp,b); 8 KB total).
// GEMM per kp: 2x LDG.128 (W hp0/hp1), 2x LDS.128 (4 batches' float2),
// 8 reg-splats pk2(x,x), 16 FFMA2.  LDS wavefronts halved vs dup layout.
// ---------------------------------------------------------------------------
__device__ __forceinline__ void rnn_body4(const int* __restrict__ x_in,
                                          int rowbase, char* smem) {
    ull* hd = reinterpret_cast<ull*>(smem);                    // [256][4] float2
    ull* pB = hd + 256 * 4;                                    // [256][34]
    int* ints = reinterpret_cast<int*>(pB + 256 * 34);
    int* orig = ints;
    int* slen = ints + 4;
    int* xi   = ints + 8;

    const int tid = threadIdx.x;
    const int grp = tid >> 7;              // 0..7
    const int u   = tid & 127;
    const int hp0 = u;
    const int hp1 = u + 128;

    // epilogue role: thread = (h-pair ehp, batch eb)
    const int ehp = tid >> 2;              // 0..255
    const int eb  = tid & 3;

    if (tid < 4) {
        orig[tid] = g_sidx[rowbase + tid];
        slen[tid] = g_slen[rowbase + tid];
    }
    for (int i = tid; i < 256 * 4; i += THR) hd[i] = 0ull;
    __syncthreads();

    int tmax = 0;
#pragma unroll
    for (int b = 0; b < 4; b++) tmax = max(tmax, slen[b]);

    const ulonglong2* Wb = reinterpret_cast<const ulonglong2*>(g_Wp);
    const int kb = grp * 32;               // kp base for this group

    ull*       wr0 = pB + hp0 * 34 + grp * 4;
    ull*       wr1 = pB + hp1 * 34 + grp * 4;
    const ull* rd  = pB + ehp * 34 + eb;

    for (int t = 0; t < tmax; t++) {
        if (tid < 4) xi[tid] = x_in[orig[tid] * S + t];
        __syncthreads();    // (1) xi ready; hd from previous epilogue visible

        // epilogue P prefetch: (P[xi[eb]][2ehp], P[xi[eb]][2ehp+1])
        float2 pf = __ldg(reinterpret_cast<const float2*>(g_P + xi[eb] * H) + ehp);

        ull a0[4], a1[4];
#pragma unroll
        for (int b = 0; b < 4; b++) { a0[b] = 0ull; a1[b] = 0ull; }

        // 32 kp, 2-kp unrolled, double-buffered W prefetch
        ulonglong2 wa0 = __ldg(Wb + (kb + 0) * HPAIR + hp0);
        ulonglong2 wa1 = __ldg(Wb + (kb + 0) * HPAIR + hp1);
        ulonglong2 wc0 = __ldg(Wb + (kb + 1) * HPAIR + hp0);
        ulonglong2 wc1 = __ldg(Wb + (kb + 1) * HPAIR + hp1);
#pragma unroll 4
        for (int c = 0; c < 32; c += 2) {
            const int n0 = (c + 2) & 31;
            const int n1 = (c + 3) & 31;
            ulonglong2 wb0 = __ldg(Wb + (kb + n0) * HPAIR + hp0);
            ulonglong2 wb1 = __ldg(Wb + (kb + n0) * HPAIR + hp1);
            {
                const float4* hk =
                    reinterpret_cast<const float4*>(hd + (unsigned)(kb + c) * 4);
                float4 qA = hk[0];   // b0:(ke,ko), b1:(ke,ko)
                float4 qB = hk[1];   // b2:(ke,ko), b3:(ke,ko)
                {   // k even
                    ull d0 = pk2(qA.x, qA.x), d1 = pk2(qA.z, qA.z);
                    ull d2 = pk2(qB.x, qB.x), d3 = pk2(qB.z, qB.z);
                    fma2(a0[0], wa0.x, d0); fma2(a0[1], wa0.x, d1);
                    fma2(a0[2], wa0.x, d2); fma2(a0[3], wa0.x, d3);
                    fma2(a1[0], wa1.x, d0); fma2(a1[1], wa1.x, d1);
                    fma2(a1[2], wa1.x, d2); fma2(a1[3], wa1.x, d3);
                }
                {   // k odd
                    ull d0 = pk2(qA.y, qA.y), d1 = pk2(qA.w, qA.w);
                    ull d2 = pk2(qB.y, qB.y), d3 = pk2(qB.w, qB.w);
                    fma2(a0[0], wa0.y, d0); fma2(a0[1], wa0.y, d1);
                    fma2(a0[2], wa0.y, d2); fma2(a0[3], wa0.y, d3);
                    fma2(a1[0], wa1.y, d0); fma2(a1[1], wa1.y, d1);
                    fma2(a1[2], wa1.y, d2); fma2(a1[3], wa1.y, d3);
                }
            }
            ulonglong2 wd0 = __ldg(Wb + (kb + n1) * HPAIR + hp0);
            ulonglong2 wd1 = __ldg(Wb + (kb + n1) * HPAIR + hp1);
            {
                const float4* hk =
                    reinterpret_cast<const float4*>(hd + (unsigned)(kb + c + 1) * 4);
                float4 qA = hk[0];
                float4 qB = hk[1];
                {   // k even
                    ull d0 = pk2(qA.x, qA.x), d1 = pk2(qA.z, qA.z);
                    ull d2 = pk2(qB.x, qB.x), d3 = pk2(qB.z, qB.z);
                    fma2(a0[0], wc0.x, d0); fma2(a0[1], wc0.x, d1);
                    fma2(a0[2], wc0.x, d2); fma2(a0[3], wc0.x, d3);
                    fma2(a1[0], wc1.x, d0); fma2(a1[1], wc1.x, d1);
                    fma2(a1[2], wc1.x, d2); fma2(a1[3], wc1.x, d3);
                }
                {   // k odd
                    ull d0 = pk2(qA.y, qA.y), d1 = pk2(qA.w, qA.w);
                    ull d2 = pk2(qB.y, qB.y), d3 = pk2(qB.w, qB.w);
                    fma2(a0[0], wc0.y, d0); fma2(a0[1], wc0.y, d1);
                    fma2(a0[2], wc0.y, d2); fma2(a0[3], wc0.y, d3);
                    fma2(a1[0], wc1.y, d0); fma2(a1[1], wc1.y, d1);
                    fma2(a1[2], wc1.y, d2); fma2(a1[3], wc1.y, d3);
                }
            }
            wa0 = wb0; wa1 = wb1; wc0 = wd0; wc1 = wd1;
        }

        // write partials: pB[hp][grp][b]
        *reinterpret_cast<ulonglong2*>(wr0)     = make_ulonglong2(a0[0], a0[1]);
        *reinterpret_cast<ulonglong2*>(wr0 + 2) = make_ulonglong2(a0[2], a0[3]);
        *reinterpret_cast<ulonglong2*>(wr1)     = make_ulonglong2(a1[0], a1[1]);
        *reinterpret_cast<ulonglong2*>(wr1 + 2) = make_ulonglong2(a1[2], a1[3]);
        __syncthreads();    // (2) partials visible; all hd reads complete

        // distributed epilogue: (h-pair ehp, batch eb)
        ull s = rd[0];
#pragma unroll
        for (int g = 1; g < 8; g++) {
            ull v = rd[g * 4];
            add2(s, s, v);
        }
        add2(s, s, pk2(pf.x, pf.y));

        float x0, x1;
        upk2(s, x0, x1);
        const float v0 = tanhf(x0);
        const float v1 = tanhf(x1);

        // non-duplicated state write: one STS.64 per thread
        hd[ehp * 4 + eb] = pk2(v0, v1);

        if (t == slen[eb] - 1)
            *reinterpret_cast<float2*>(g_last + orig[eb] * H + 2 * ehp) =
                make_float2(v0, v1);
    }
}

// ---------------------------------------------------------------------------
// Kernel 4: bucketed persistent RNN.
//   bid 0..103   : NB=4, rows 608 + 4*bid (longest 416 rows)
//   bid 104..179 : NB=8, rows 600 - 8*(bid-104) (descending; shortest last)
// ---------------------------------------------------------------------------
__global__ void __launch_bounds__(THR, 1) rnn_kernel(const int* __restrict__ x_in) {
    extern __shared__ char smem[];
    const int bid = blockIdx.x;
    if (bid < N_CTA4) {
        rnn_body4(x_in, 608 + 4 * bid, smem);
    } else {
        rnn_body8(x_in, 600 - 8 * (bid - N_CTA4), smem);
    }
}

// ---------------------------------------------------------------------------
// Kernel 5: MLP head — one rnn-style NB=8 step (relu) + k-split logits.
// ---------------------------------------------------------------------------
__global__ void __launch_bounds__(THR, 1) mlp_kernel(const float* __restrict__ b1,
                                                     const float* __restrict__ b2,
                                                     float* __restrict__ out) {
    extern __shared__ char smem[];
    ull*   hT2  = reinterpret_cast<ull*>(smem + MLP_HT2);    // [512][4]
    ull*   pB   = reinterpret_cast<ull*>(smem + MLP_PB);     // [256][34]
    float* hlin = reinterpret_cast<float*>(smem + MLP_HLIN); // [8][512]
    float* red  = reinterpret_cast<float*>(smem + MLP_RED);  // [256][5]

    const int tid  = threadIdx.x;
    const int grp  = tid >> 8;
    const int hp   = tid & (HPAIR - 1);
    const int base = blockIdx.x * BT;

    const int eh   = tid >> 1;
    const int eq   = tid & 1;
    const int ehp  = eh >> 1;
    const int epar = eh & 1;

    hT2[eh * 4 + 2 * eq + 0] = pk2(g_last[(base + 4 * eq + 0) * H + eh],
                                   g_last[(base + 4 * eq + 1) * H + eh]);
    hT2[eh * 4 + 2 * eq + 1] = pk2(g_last[(base + 4 * eq + 2) * H + eh],
                                   g_last[(base + 4 * eq + 3) * H + eh]);
    __syncthreads();

    const ulonglong2* Wp =
        reinterpret_cast<const ulonglong2*>(g_W1p) + (grp * 64) * HPAIR + hp;

    ull a0[4], a1[4];
#pragma unroll
    for (int p = 0; p < 4; p++) { a0[p] = 0ull; a1[p] = 0ull; }

    gemm_g6<8>(Wp, hT2, grp * 128, a0, a1);

    ull* myPB = pB + hp * 34 + grp * 8;
#pragma unroll
    for (int p = 0; p < 4; p += 2)
        *reinterpret_cast<ulonglong2*>(myPB + p) = make_ulonglong2(a0[p], a0[p + 1]);
#pragma unroll
    for (int p = 0; p < 4; p += 2)
        *reinterpret_cast<ulonglong2*>(myPB + 4 + p) = make_ulonglong2(a1[p], a1[p + 1]);
    __syncthreads();

    {
        const ull* ePB = pB + ehp * 34 + epar * 4 + eq * 2;
        ull s[2];
#pragma unroll
        for (int q = 0; q < 2; q++) s[q] = ePB[q];
#pragma unroll
        for (int g = 1; g < 4; g++) {
#pragma unroll
            for (int q = 0; q < 2; q++) {
                ull v = ePB[g * 8 + q];
                add2(s[q], s[q], v);
            }
        }
        const float bv = __ldg(b1 + eh);
#pragma unroll
        for (int q = 0; q < 2; q++) {
            float x, y;
            upk2(s[q], x, y);
            hlin[(eq * 4 + 2 * q + 0) * H + eh] = fmaxf(x + bv, 0.f);
            hlin[(eq * 4 + 2 * q + 1) * H + eh] = fmaxf(y + bv, 0.f);
        }
    }
    __syncthreads();

    {
        const int kq = tid >> 8;
        const int r  = tid & 255;
        const int b  = r >> 5;
        const int c  = r & 31;
        float acc = 0.f;
        const float* hb = hlin + b * H + kq * 128;
        const float* w2 = g_W2T + (kq * 128) * C + c;
#pragma unroll 8
        for (int k = 0; k < 128; k++) acc += hb[k] * __ldg(w2 + k * C);
        red[r * 5 + kq] = acc;
    }
    __syncthreads();

    if (tid < 256) {
        const int b = tid >> 5, c = tid & 31;
        float acc = __ldg(b2 + c) + red[tid * 5 + 0] + red[tid * 5 + 1]
                  + red[tid * 5 + 2] + red[tid * 5 + 3];
        out[(base + b) * C + c] = acc;
    }
}

// ---------------------------------------------------------------------------
extern "C" void kernel_launch(void* const* d_in, const int* in_sizes, int n_in,
                              void* d_out, int out_size) {
    const int*   x_in   = (const int*)  d_in[0];
    const int*   x_lens = (const int*)  d_in[1];
    const float* emb    = (const float*)d_in[2];
    const float* W_ih   = (const float*)d_in[3];
    const float* b_ih   = (const float*)d_in[4];
    const float* W_hh   = (const float*)d_in[5];
    const float* b_hh   = (const float*)d_in[6];
    const float* W1w    = (const float*)d_in[7];
    const float* b1     = (const float*)d_in[8];
    const float* W2w    = (const float*)d_in[9];
    const float* b2     = (const float*)d_in[10];
    float* out = (float*)d_out;

    cudaFuncSetAttribute(rnn_kernel,
                         cudaFuncAttributeMaxDynamicSharedMemorySize, RNN_SMEM);
    cudaFuncSetAttribute(mlp_kernel,
                         cudaFuncAttributeMaxDynamicSharedMemorySize, MLP_SMEM);

    precompute_P<<<V, H>>>(emb, W_ih, b_ih, b_hh);
    sort_by_len<<<16, 64>>>(x_lens);
    int tgrid = (2 * H * H + C * H + 255) / 256;
    transpose_all<<<tgrid, 256>>>(W_hh, W1w, W2w);
    rnn_kernel<<<RNN_GRID, THR, RNN_SMEM>>>(x_in);
    mlp_kernel<<<B / BT, THR, MLP_SMEM>>>(b1, b2, out);
}